// round 1
// baseline (speedup 1.0000x reference)
#include <cuda_runtime.h>
#include <math.h>

#define H_ 8
#define D_ 64
#define G_ 64
#define DIM_ 256
#define INNER_ 512
#define B_ 4
#define NPTS 32768
#define BH_ (B_*H_)
#define SPLITS 32

// ---------------- scratch (static device allocations; no cudaMalloc) ----------------
__device__ float g_fx[(size_t)B_ * NPTS * INNER_];      // 268 MB
__device__ float g_sw[(size_t)B_ * NPTS * INNER_];      // 268 MB
__device__ float g_WfxT[DIM_ * INNER_];
__device__ float g_WcombT[DIM_ * INNER_];
__device__ float g_lbias[INNER_];
__device__ float g_part[(size_t)BH_ * SPLITS * G_ * D_];
__device__ float g_psn[(size_t)BH_ * SPLITS * G_];
__device__ float g_st[(size_t)BH_ * G_ * D_];
__device__ float g_kn[(size_t)B_ * G_ * D_];
__device__ float g_v[(size_t)B_ * G_ * D_];
__device__ float g_M[(size_t)B_ * INNER_ * DIM_];

// ---------------- prep: transpose Wfx; fold Wslice into Wx; combined logit bias ----
__global__ __launch_bounds__(256) void prep_k(
    const float* __restrict__ Wfx, const float* __restrict__ Wx,
    const float* __restrict__ Wslice, const float* __restrict__ bx,
    const float* __restrict__ bslice)
{
    int idx = blockIdx.x * 256 + threadIdx.x;       // 0 .. 131071
    int n = idx >> 8;                               // output column (h*64+g), 0..511
    int k = idx & 255;                              // input dim, 0..255
    g_WfxT[k * INNER_ + n] = Wfx[idx];              // Wfx[n,k] -> WfxT[k,n]
    int h = n >> 6, g = n & 63;
    float s = 0.f;
    #pragma unroll 16
    for (int d = 0; d < 64; d++)
        s += Wslice[g * 64 + d] * Wx[(h * 64 + d) * DIM_ + k];
    g_WcombT[k * INNER_ + n] = s;
    if (k == 0) {
        float sb = 0.f;
        for (int d = 0; d < 64; d++) sb += Wslice[g * 64 + d] * bx[h * 64 + d];
        g_lbias[n] = sb + bslice[g];
    }
}

// ---------------- main GEMM: C[M,N] = A[M,K] @ Bm[K,N] + bias; optional fused
// per-64-col softmax epilogue (col block of 128 = two heads). 128x128x16 tile,
// 256 threads, 8x8 per thread. All dims divisible (M%128==0, N%128==0, K%16==0).
template<bool SOFTMAX>
__global__ __launch_bounds__(256) void gemm_k(
    const float* __restrict__ A, const float* __restrict__ Bm,
    const float* __restrict__ bias, float* __restrict__ C,
    int N, int K, const float* __restrict__ temp,
    long sA, long sB, long sC)
{
    A += (long)blockIdx.z * sA;
    Bm += (long)blockIdx.z * sB;
    C += (long)blockIdx.z * sC;

    __shared__ float As[16][136];   // [k][m], pad 8 (keeps float4 alignment)
    __shared__ float Bs[16][128];   // [k][n]

    const int tid = threadIdx.x;
    const int tx = tid & 15;        // 16 col groups * 8
    const int ty = tid >> 4;        // 16 row groups * 8
    const int rowBase = blockIdx.x * 128;
    const int colBase = blockIdx.y * 128;

    float acc[8][8] = {};

    for (int kt = 0; kt < K; kt += 16) {
        #pragma unroll
        for (int l = 0; l < 2; l++) {
            int f = tid * 2 + l;            // 0..511
            int r = f >> 2;                 // 0..127
            int kq = (f & 3) << 2;          // 0,4,8,12
            float4 av = *reinterpret_cast<const float4*>(
                A + (long)(rowBase + r) * K + kt + kq);
            As[kq + 0][r] = av.x; As[kq + 1][r] = av.y;
            As[kq + 2][r] = av.z; As[kq + 3][r] = av.w;
        }
        #pragma unroll
        for (int l = 0; l < 2; l++) {
            int f = tid * 2 + l;
            int kr = f >> 5;                // 0..15
            int nq = (f & 31) << 2;         // 0..124
            *reinterpret_cast<float4*>(&Bs[kr][nq]) =
                *reinterpret_cast<const float4*>(
                    Bm + (long)(kt + kr) * N + colBase + nq);
        }
        __syncthreads();
        #pragma unroll
        for (int kk = 0; kk < 16; kk++) {
            float a[8], b[8];
            float4 a0 = *reinterpret_cast<const float4*>(&As[kk][ty * 8]);
            float4 a1 = *reinterpret_cast<const float4*>(&As[kk][ty * 8 + 4]);
            a[0]=a0.x; a[1]=a0.y; a[2]=a0.z; a[3]=a0.w;
            a[4]=a1.x; a[5]=a1.y; a[6]=a1.z; a[7]=a1.w;
            float4 b0 = *reinterpret_cast<const float4*>(&Bs[kk][tx * 8]);
            float4 b1 = *reinterpret_cast<const float4*>(&Bs[kk][tx * 8 + 4]);
            b[0]=b0.x; b[1]=b0.y; b[2]=b0.z; b[3]=b0.w;
            b[4]=b1.x; b[5]=b1.y; b[6]=b1.z; b[7]=b1.w;
            #pragma unroll
            for (int i = 0; i < 8; i++)
                #pragma unroll
                for (int j = 0; j < 8; j++)
                    acc[i][j] += a[i] * b[j];
        }
        __syncthreads();
    }

    float bias8[8];
    #pragma unroll
    for (int j = 0; j < 8; j++) bias8[j] = bias[colBase + tx * 8 + j];

    if (!SOFTMAX) {
        #pragma unroll
        for (int i = 0; i < 8; i++) {
            float4 o0, o1;
            o0.x = acc[i][0] + bias8[0]; o0.y = acc[i][1] + bias8[1];
            o0.z = acc[i][2] + bias8[2]; o0.w = acc[i][3] + bias8[3];
            o1.x = acc[i][4] + bias8[4]; o1.y = acc[i][5] + bias8[5];
            o1.z = acc[i][6] + bias8[6]; o1.w = acc[i][7] + bias8[7];
            long off = (long)(rowBase + ty * 8 + i) * N + colBase + tx * 8;
            *reinterpret_cast<float4*>(C + off) = o0;
            *reinterpret_cast<float4*>(C + off + 4) = o1;
        }
    } else {
        // this block's 128 cols = heads (2*blockIdx.y, 2*blockIdx.y+1);
        // a 64-col head-row is owned by 8 lanes (tx within one half) -> shfl reduce
        const float invt = 1.0f / temp[blockIdx.y * 2 + (tx >> 3)];
        #pragma unroll
        for (int i = 0; i < 8; i++) {
            float v[8];
            float m = -1e30f;
            #pragma unroll
            for (int j = 0; j < 8; j++) {
                v[j] = (acc[i][j] + bias8[j]) * invt;
                m = fmaxf(m, v[j]);
            }
            #pragma unroll
            for (int o = 4; o > 0; o >>= 1)
                m = fmaxf(m, __shfl_xor_sync(0xffffffffu, m, o));
            float s = 0.f;
            #pragma unroll
            for (int j = 0; j < 8; j++) { v[j] = __expf(v[j] - m); s += v[j]; }
            #pragma unroll
            for (int o = 4; o > 0; o >>= 1)
                s += __shfl_xor_sync(0xffffffffu, s, o);
            const float inv = 1.0f / s;
            float4 o0, o1;
            o0.x=v[0]*inv; o0.y=v[1]*inv; o0.z=v[2]*inv; o0.w=v[3]*inv;
            o1.x=v[4]*inv; o1.y=v[5]*inv; o1.z=v[6]*inv; o1.w=v[7]*inv;
            long off = (long)(rowBase + ty * 8 + i) * N + colBase + tx * 8;
            *reinterpret_cast<float4*>(C + off) = o0;
            *reinterpret_cast<float4*>(C + off + 4) = o1;
        }
    }
}

// ---------------- pooling: per (b,h,split): partial st = sw^T @ fx [64x64], + col sums
__global__ __launch_bounds__(256) void pool_k()
{
    const int s = blockIdx.x;
    const int bh = blockIdx.y;
    const int b = bh >> 3, h = bh & 7;
    const int tid = threadIdx.x;
    const int cx = tid & 15, gy = tid >> 4;
    __shared__ float Ss[16][64];
    __shared__ float Sf[16][64];
    float acc[4][4] = {};
    float sn = 0.f;
    const int chunk = NPTS / SPLITS;  // 1024
    const long base = (long)b * NPTS * INNER_ + h * 64;
    const int r = tid >> 4, g4 = (tid & 15) << 2;

    for (int n0 = s * chunk; n0 < (s + 1) * chunk; n0 += 16) {
        long addr = base + (long)(n0 + r) * INNER_ + g4;
        *reinterpret_cast<float4*>(&Ss[r][g4]) =
            *reinterpret_cast<const float4*>(g_sw + addr);
        *reinterpret_cast<float4*>(&Sf[r][g4]) =
            *reinterpret_cast<const float4*>(g_fx + addr);
        __syncthreads();
        #pragma unroll
        for (int kk = 0; kk < 16; kk++) {
            float4 a4 = *reinterpret_cast<const float4*>(&Ss[kk][gy << 2]);
            float4 b4 = *reinterpret_cast<const float4*>(&Sf[kk][cx << 2]);
            float a[4] = {a4.x, a4.y, a4.z, a4.w};
            float bb[4] = {b4.x, b4.y, b4.z, b4.w};
            #pragma unroll
            for (int i = 0; i < 4; i++)
                #pragma unroll
                for (int j = 0; j < 4; j++)
                    acc[i][j] += a[i] * bb[j];
        }
        if (tid < 64) {
            #pragma unroll
            for (int kk = 0; kk < 16; kk++) sn += Ss[kk][tid];
        }
        __syncthreads();
    }
    long pbase = ((long)bh * SPLITS + s) * 4096;
    #pragma unroll
    for (int i = 0; i < 4; i++)
        #pragma unroll
        for (int j = 0; j < 4; j++)
            g_part[pbase + (gy * 4 + i) * 64 + cx * 4 + j] = acc[i][j];
    if (tid < 64) g_psn[((long)bh * SPLITS + s) * 64 + tid] = sn;
}

// ---------------- deterministic split reduce + snorm divide -> st[b,h,g,d]
__global__ __launch_bounds__(256) void reduce_k()
{
    const int bh = blockIdx.x;
    const int tid = threadIdx.x;
    __shared__ float inv_sn[64];
    if (tid < 64) {
        float s = 0.f;
        #pragma unroll
        for (int sp = 0; sp < SPLITS; sp++)
            s += g_psn[((long)bh * SPLITS + sp) * 64 + tid];
        inv_sn[tid] = 1.0f / (s + 1e-5f);
    }
    __syncthreads();
    for (int e = tid; e < 4096; e += 256) {
        float s = 0.f;
        #pragma unroll
        for (int sp = 0; sp < SPLITS; sp++)
            s += g_part[((long)bh * SPLITS + sp) * 4096 + e];
        g_st[(long)bh * 4096 + e] = s * inv_sn[e >> 6];
    }
}

// ---------------- kv = mean_h st; k=kv@Wk^T (row-normalized); v=kv@Wv^T
__global__ __launch_bounds__(256) void kv_k(
    const float* __restrict__ Wk, const float* __restrict__ Wv)
{
    __shared__ float kv[4096];
    __shared__ float kb[4096];
    __shared__ float rn[64];
    const int b = blockIdx.x;
    const int tid = threadIdx.x;
    for (int e = tid; e < 4096; e += 256) {
        float s = 0.f;
        #pragma unroll
        for (int h = 0; h < 8; h++) s += g_st[(long)(b * 8 + h) * 4096 + e];
        kv[e] = s * 0.125f;
    }
    __syncthreads();
    {
        const int d = tid & 63;
        const float4* wkp = reinterpret_cast<const float4*>(Wk + d * 64);
        const float4* wvp = reinterpret_cast<const float4*>(Wv + d * 64);
        #pragma unroll
        for (int k = 0; k < 16; k++) {
            int g = (tid >> 6) + k * 4;
            const float4* kvp = reinterpret_cast<const float4*>(kv + g * 64);
            float sk = 0.f, sv = 0.f;
            #pragma unroll
            for (int e4 = 0; e4 < 16; e4++) {
                float4 x = kvp[e4];
                float4 wk4 = wkp[e4], wv4 = wvp[e4];
                sk += x.x * wk4.x + x.y * wk4.y + x.z * wk4.z + x.w * wk4.w;
                sv += x.x * wv4.x + x.y * wv4.y + x.z * wv4.z + x.w * wv4.w;
            }
            kb[g * 64 + d] = sk;
            g_v[(long)b * 4096 + g * 64 + d] = sv;
        }
    }
    __syncthreads();
    if (tid < 64) {
        float s = 0.f;
        for (int d = 0; d < 64; d++) { float x = kb[tid * 64 + d]; s += x * x; }
        rn[tid] = 1.0f / fmaxf(sqrtf(s), 1e-12f);
    }
    __syncthreads();
    for (int e = tid; e < 4096; e += 256)
        g_kn[(long)b * 4096 + e] = kb[e] * rn[e >> 6];
}

// ---------------- per (b,h): q-normalized cross attention over slice tokens,
// residual, and fold Wout: M[b, h*64+g, :] = out_st[g,:] @ Wout_h^T
__global__ __launch_bounds__(256) void attn_k(
    const float* __restrict__ Wq, const float* __restrict__ Wout,
    const float* __restrict__ attn_scale, const float* __restrict__ res_scale)
{
    extern __shared__ float sm[];
    float* sst = sm;            // [64][64] st, later out_st
    float* sq  = sm + 4096;     // [64][64] q/qn, later v
    float* sc  = sm + 8192;     // [64][65] scores
    const int bh = blockIdx.x;
    const int b = bh >> 3, h = bh & 7;
    const int tid = threadIdx.x;

    for (int e = tid; e < 4096; e += 256) sst[e] = g_st[(long)bh * 4096 + e];
    __syncthreads();

    {   // q = st @ Wq^T
        const int d = tid & 63;
        const float4* wp = reinterpret_cast<const float4*>(Wq + d * 64);
        #pragma unroll
        for (int k = 0; k < 16; k++) {
            int g = (tid >> 6) + k * 4;
            const float4* sp = reinterpret_cast<const float4*>(sst + g * 64);
            float s = 0.f;
            #pragma unroll
            for (int e4 = 0; e4 < 16; e4++) {
                float4 w = wp[e4], x = sp[e4];
                s += w.x * x.x + w.y * x.y + w.z * x.z + w.w * x.w;
            }
            sq[g * 64 + d] = s;
        }
    }
    __syncthreads();
    if (tid < 64) {   // normalize q rows in place
        float s = 0.f;
        for (int d = 0; d < 64; d++) { float x = sq[tid * 64 + d]; s += x * x; }
        float inv = 1.0f / fmaxf(sqrtf(s), 1e-12f);
        for (int d = 0; d < 64; d++) sq[tid * 64 + d] *= inv;
    }
    __syncthreads();
    {   // scores = qn @ kn^T * attn_scale
        const float asc = attn_scale[h];
        const int ss = tid & 63;
        const float4* kp = reinterpret_cast<const float4*>(g_kn + (long)b * 4096 + ss * 64);
        #pragma unroll
        for (int k = 0; k < 16; k++) {
            int g = (tid >> 6) + k * 4;
            const float4* qp = reinterpret_cast<const float4*>(sq + g * 64);
            float s = 0.f;
            #pragma unroll
            for (int d4 = 0; d4 < 16; d4++) {
                float4 kk = kp[d4], qq = qp[d4];
                s += kk.x * qq.x + kk.y * qq.y + kk.z * qq.z + kk.w * qq.w;
            }
            sc[g * 65 + ss] = s * asc;
        }
    }
    __syncthreads();
    if (tid < 64) {   // row softmax over 64 slice tokens
        float m = -1e30f;
        for (int s = 0; s < 64; s++) m = fmaxf(m, sc[tid * 65 + s]);
        float sum = 0.f;
        for (int s = 0; s < 64; s++) {
            float e = __expf(sc[tid * 65 + s] - m);
            sc[tid * 65 + s] = e; sum += e;
        }
        float inv = 1.0f / sum;
        for (int s = 0; s < 64; s++) sc[tid * 65 + s] *= inv;
    }
    // overlap: load v into sq (qn is dead)
    for (int e = tid; e < 4096; e += 256) sq[e] = g_v[(long)b * 4096 + e];
    __syncthreads();

    const float res = *res_scale;
    float outreg[16];
    {   // out_st = attn @ v + res*st
        const int d = tid & 63;
        #pragma unroll
        for (int k = 0; k < 16; k++) {
            int g = (tid >> 6) + k * 4;
            float s = 0.f;
            #pragma unroll 16
            for (int ss = 0; ss < 64; ss++)
                s += sc[g * 65 + ss] * sq[ss * 64 + d];
            outreg[k] = s + res * sst[g * 64 + d];
        }
    }
    __syncthreads();
    {   // write out_st into sst
        const int d = tid & 63;
        #pragma unroll
        for (int k = 0; k < 16; k++)
            sst[((tid >> 6) + k * 4) * 64 + d] = outreg[k];
    }
    __syncthreads();
    {   // M[b, h*64+g, c] = sum_d out_st[g,d] * Wout[c, h*64+d]
        const int c = tid;   // 0..255
        const float4* wp = reinterpret_cast<const float4*>(Wout + c * INNER_ + h * 64);
        for (int g = 0; g < 64; g++) {
            const float4* op = reinterpret_cast<const float4*>(sst + g * 64);
            float s = 0.f;
            #pragma unroll
            for (int d4 = 0; d4 < 16; d4++) {
                float4 w = wp[d4], o = op[d4];
                s += w.x * o.x + w.y * o.y + w.z * o.z + w.w * o.w;
            }
            g_M[((long)b * INNER_ + h * 64 + g) * DIM_ + c] = s;
        }
    }
}

// ---------------- host launcher ----------------
extern "C" void kernel_launch(void* const* d_in, const int* in_sizes, int n_in,
                              void* d_out, int out_size)
{
    const float* x         = (const float*)d_in[0];
    const float* Wfx       = (const float*)d_in[1];
    const float* bfx       = (const float*)d_in[2];
    const float* Wx        = (const float*)d_in[3];
    const float* bx        = (const float*)d_in[4];
    const float* Wslice    = (const float*)d_in[5];
    const float* bslice    = (const float*)d_in[6];
    const float* temp      = (const float*)d_in[7];
    const float* Wq        = (const float*)d_in[8];
    const float* Wk        = (const float*)d_in[9];
    const float* Wv        = (const float*)d_in[10];
    const float* res_scale = (const float*)d_in[11];
    const float* attn_scl  = (const float*)d_in[12];
    const float* Wout      = (const float*)d_in[13];
    const float* bout      = (const float*)d_in[14];
    float* out = (float*)d_out;

    float *p_fx, *p_sw, *p_WfxT, *p_WcombT, *p_lbias, *p_M;
    cudaGetSymbolAddress((void**)&p_fx, g_fx);
    cudaGetSymbolAddress((void**)&p_sw, g_sw);
    cudaGetSymbolAddress((void**)&p_WfxT, g_WfxT);
    cudaGetSymbolAddress((void**)&p_WcombT, g_WcombT);
    cudaGetSymbolAddress((void**)&p_lbias, g_lbias);
    cudaGetSymbolAddress((void**)&p_M, g_M);

    cudaFuncSetAttribute(attn_k, cudaFuncAttributeMaxDynamicSharedMemorySize, 49408);

    prep_k<<<512, 256>>>(Wfx, Wx, Wslice, bx, bslice);

    // fx = x @ Wfx^T + bfx
    gemm_k<false><<<dim3(1024, 4, 1), 256>>>(
        x, p_WfxT, bfx, p_fx, INNER_, DIM_, nullptr, 0, 0, 0);

    // sw = softmax_G((x @ Wcomb^T + lbias) / temp[h])   (fused epilogue)
    gemm_k<true><<<dim3(1024, 4, 1), 256>>>(
        x, p_WcombT, p_lbias, p_sw, INNER_, DIM_, temp, 0, 0, 0);

    pool_k<<<dim3(SPLITS, BH_), 256>>>();
    reduce_k<<<BH_, 256>>>();
    kv_k<<<B_, 256>>>(Wk, Wv);
    attn_k<<<BH_, 256, 49408>>>(Wq, Wout, attn_scl, res_scale);

    // out = sw @ M[b] + bout   (scatter + Wout projection folded)
    gemm_k<false><<<dim3(256, 2, B_), 256>>>(
        p_sw, p_M, bout, out, DIM_, INNER_, nullptr,
        (long)NPTS * INNER_, (long)INNER_ * DIM_, (long)NPTS * DIM_);
}

// round 2
// speedup vs baseline: 1.5909x; 1.5909x over previous
#include <cuda_runtime.h>
#include <cuda_bf16.h>
#include <math.h>
#include <stdint.h>

#define H_ 8
#define D_ 64
#define G_ 64
#define DIM_ 256
#define INNER_ 512
#define B_ 4
#define NPTS 32768
#define BH_ (B_*H_)
#define SPLITS 32
#define LDA 40   // smem row stride (bf16 elems) for 32-wide k-stage, conflict-mitigating pad

using bf16 = __nv_bfloat16;

// ---------------- scratch (static device allocations; no cudaMalloc) ----------------
__device__ bf16 g_fxHi[(size_t)B_ * NPTS * INNER_];   // 134 MB
__device__ bf16 g_fxLo[(size_t)B_ * NPTS * INNER_];
__device__ bf16 g_swHi[(size_t)B_ * NPTS * INNER_];
__device__ bf16 g_swLo[(size_t)B_ * NPTS * INNER_];
__device__ bf16 g_WfxHi[INNER_ * DIM_];
__device__ bf16 g_WfxLo[INNER_ * DIM_];
__device__ bf16 g_WcombHi[INNER_ * DIM_];
__device__ bf16 g_WcombLo[INNER_ * DIM_];
__device__ float g_lbias[INNER_];
__device__ float g_part[(size_t)BH_ * SPLITS * G_ * D_];
__device__ float g_psn[(size_t)BH_ * SPLITS * G_];
__device__ float g_st[(size_t)BH_ * G_ * D_];
__device__ float g_kn[(size_t)B_ * G_ * D_];
__device__ float g_v[(size_t)B_ * G_ * D_];
__device__ float g_M[(size_t)B_ * DIM_ * INNER_];     // [b][c][inner]  ([N][K] for mma)
__device__ bf16 g_MHi[(size_t)B_ * DIM_ * INNER_];
__device__ bf16 g_MLo[(size_t)B_ * DIM_ * INNER_];

// ---------------- helpers ----------------
__device__ __forceinline__ void split1(float v, bf16& h, bf16& l) {
    h = __float2bfloat16(v);
    l = __float2bfloat16(v - __bfloat162float(h));
}

__device__ __forceinline__ uint32_t sptr(const void* p) {
    return (uint32_t)__cvta_generic_to_shared(p);
}

__device__ __forceinline__ void ldsm4(uint32_t* r, uint32_t addr) {
    asm volatile("ldmatrix.sync.aligned.m8n8.x4.shared.b16 {%0,%1,%2,%3}, [%4];"
                 : "=r"(r[0]), "=r"(r[1]), "=r"(r[2]), "=r"(r[3]) : "r"(addr));
}

__device__ __forceinline__ void mma16816(float* d, const uint32_t* a, const uint32_t* b) {
    asm volatile("mma.sync.aligned.m16n8k16.row.col.f32.bf16.bf16.f32 "
                 "{%0,%1,%2,%3}, {%4,%5,%6,%7}, {%8,%9}, {%0,%1,%2,%3};"
                 : "+f"(d[0]), "+f"(d[1]), "+f"(d[2]), "+f"(d[3])
                 : "r"(a[0]), "r"(a[1]), "r"(a[2]), "r"(a[3]), "r"(b[0]), "r"(b[1]));
}

__device__ __forceinline__ float4 loadpair4(const bf16* hi, const bf16* lo, long off) {
    uint2 h = *reinterpret_cast<const uint2*>(hi + off);
    uint2 l = *reinterpret_cast<const uint2*>(lo + off);
    float2 h0 = __bfloat1622float2(*reinterpret_cast<const __nv_bfloat162*>(&h.x));
    float2 h1 = __bfloat1622float2(*reinterpret_cast<const __nv_bfloat162*>(&h.y));
    float2 l0 = __bfloat1622float2(*reinterpret_cast<const __nv_bfloat162*>(&l.x));
    float2 l1 = __bfloat1622float2(*reinterpret_cast<const __nv_bfloat162*>(&l.y));
    return make_float4(h0.x + l0.x, h0.y + l0.y, h1.x + l1.x, h1.y + l1.y);
}

// ---------------- prep: split Wfx; fold Wslice into Wx -> Wcomb [N][K]; logit bias ----
__global__ __launch_bounds__(256) void prep_k(
    const float* __restrict__ Wfx, const float* __restrict__ Wx,
    const float* __restrict__ Wslice, const float* __restrict__ bx,
    const float* __restrict__ bslice)
{
    int idx = blockIdx.x * 256 + threadIdx.x;       // 0 .. 131071
    int n = idx >> 8;                               // output col (h*64+g)
    int k = idx & 255;                              // input dim
    split1(Wfx[idx], g_WfxHi[idx], g_WfxLo[idx]);   // Wfx is already [N][K]
    int h = n >> 6, g = n & 63;
    float s = 0.f;
    #pragma unroll 16
    for (int d = 0; d < 64; d++)
        s += Wslice[g * 64 + d] * Wx[(h * 64 + d) * DIM_ + k];
    split1(s, g_WcombHi[idx], g_WcombLo[idx]);
    if (k == 0) {
        float sb = 0.f;
        for (int d = 0; d < 64; d++) sb += Wslice[g * 64 + d] * bx[h * 64 + d];
        g_lbias[n] = sb + bslice[g];
    }
}

// ---------------- tensor-core GEMM: C[M,N] = A[M,K] @ B^T  (B stored [N][K])
// split-bf16 3-term (AhiBhi + AhiBlo + AloBhi), fp32 accumulate.
// 128x128 tile, 256 threads (8 warps, 2x4), warp tile 64x32, k-stage 32.
template<bool A_F32, bool SOFTMAX, bool OUT_PAIR>
__global__ __launch_bounds__(256) void mma_gemm(
    const float* __restrict__ Af,
    const bf16* __restrict__ Ahi, const bf16* __restrict__ Alo,
    const bf16* __restrict__ Bhi, const bf16* __restrict__ Blo,
    const float* __restrict__ bias, const float* __restrict__ temp,
    float* __restrict__ C, bf16* __restrict__ Chi, bf16* __restrict__ Clo,
    int N, int K, long sA, long sB, long sC)
{
    __shared__ alignas(16) bf16 sAhi[128 * LDA];
    __shared__ alignas(16) bf16 sAlo[128 * LDA];
    __shared__ alignas(16) bf16 sBhi[128 * LDA];
    __shared__ alignas(16) bf16 sBlo[128 * LDA];
    __shared__ float red[2][4][128];

    const int tid = threadIdx.x;
    const int lane = tid & 31;
    const int wid = tid >> 5;
    const int warpM = wid & 1;      // 0..1 (64-row halves)
    const int warpN = wid >> 1;     // 0..3 (32-col quarters)
    const long rowBase = (long)blockIdx.x * 128;
    const int colBase = blockIdx.y * 128;

    if (A_F32) { Af += (long)blockIdx.z * sA; }
    else       { Ahi += (long)blockIdx.z * sA; Alo += (long)blockIdx.z * sA; }
    Bhi += (long)blockIdx.z * sB; Blo += (long)blockIdx.z * sB;
    if (OUT_PAIR) { Chi += (long)blockIdx.z * sC; Clo += (long)blockIdx.z * sC; }
    else          { C += (long)blockIdx.z * sC; }

    float acc[4][4][4];
    #pragma unroll
    for (int i = 0; i < 4; i++)
        #pragma unroll
        for (int j = 0; j < 4; j++)
            #pragma unroll
            for (int q = 0; q < 4; q++) acc[i][j][q] = 0.f;

    for (int kt = 0; kt < K; kt += 32) {
        #pragma unroll
        for (int l = 0; l < 4; l++) {
            int f = l * 256 + tid;          // 0..1023
            int r = f >> 3;                 // 0..127
            int c4 = (f & 7) << 2;          // 0..28
            if (A_F32) {
                float4 v = *reinterpret_cast<const float4*>(
                    Af + (rowBase + r) * K + kt + c4);
                bf16 hx, lx, hy, ly, hz, lz, hw, lw;
                split1(v.x, hx, lx); split1(v.y, hy, ly);
                split1(v.z, hz, lz); split1(v.w, hw, lw);
                *reinterpret_cast<__nv_bfloat162*>(&sAhi[r * LDA + c4])     = __nv_bfloat162(hx, hy);
                *reinterpret_cast<__nv_bfloat162*>(&sAhi[r * LDA + c4 + 2]) = __nv_bfloat162(hz, hw);
                *reinterpret_cast<__nv_bfloat162*>(&sAlo[r * LDA + c4])     = __nv_bfloat162(lx, ly);
                *reinterpret_cast<__nv_bfloat162*>(&sAlo[r * LDA + c4 + 2]) = __nv_bfloat162(lz, lw);
            } else {
                *reinterpret_cast<uint2*>(&sAhi[r * LDA + c4]) =
                    *reinterpret_cast<const uint2*>(Ahi + (rowBase + r) * K + kt + c4);
                *reinterpret_cast<uint2*>(&sAlo[r * LDA + c4]) =
                    *reinterpret_cast<const uint2*>(Alo + (rowBase + r) * K + kt + c4);
            }
            *reinterpret_cast<uint2*>(&sBhi[r * LDA + c4]) =
                *reinterpret_cast<const uint2*>(Bhi + (long)(colBase + r) * K + kt + c4);
            *reinterpret_cast<uint2*>(&sBlo[r * LDA + c4]) =
                *reinterpret_cast<const uint2*>(Blo + (long)(colBase + r) * K + kt + c4);
        }
        __syncthreads();

        #pragma unroll
        for (int kh = 0; kh < 2; kh++) {
            uint32_t ah[4][4], al[4][4], bh[4][2], bl[4][2];
            #pragma unroll
            for (int mi = 0; mi < 4; mi++) {
                int rrow = warpM * 64 + mi * 16 + (lane & 15);
                int ccol = kh * 16 + ((lane >> 4) << 3);
                ldsm4(ah[mi], sptr(&sAhi[rrow * LDA + ccol]));
                ldsm4(al[mi], sptr(&sAlo[rrow * LDA + ccol]));
            }
            #pragma unroll
            for (int p = 0; p < 2; p++) {
                int nrow = warpN * 32 + p * 16 + ((lane & 7) | (((lane >> 4) & 1) << 3));
                int ccol = kh * 16 + (((lane >> 3) & 1) << 3);
                uint32_t t[4];
                ldsm4(t, sptr(&sBhi[nrow * LDA + ccol]));
                bh[2*p][0] = t[0]; bh[2*p][1] = t[1];
                bh[2*p+1][0] = t[2]; bh[2*p+1][1] = t[3];
                ldsm4(t, sptr(&sBlo[nrow * LDA + ccol]));
                bl[2*p][0] = t[0]; bl[2*p][1] = t[1];
                bl[2*p+1][0] = t[2]; bl[2*p+1][1] = t[3];
            }
            #pragma unroll
            for (int mi = 0; mi < 4; mi++)
                #pragma unroll
                for (int ni = 0; ni < 4; ni++) {
                    mma16816(acc[mi][ni], ah[mi], bh[ni]);
                    mma16816(acc[mi][ni], ah[mi], bl[ni]);
                    mma16816(acc[mi][ni], al[mi], bh[ni]);
                }
        }
        __syncthreads();
    }

    // ---- epilogue ----
    float bc0[4], bc1[4];
    #pragma unroll
    for (int ni = 0; ni < 4; ni++) {
        int col = colBase + warpN * 32 + ni * 8 + (lane & 3) * 2;
        bc0[ni] = bias[col]; bc1[ni] = bias[col + 1];
    }

    if (SOFTMAX) {
        const float invt = 1.0f / temp[blockIdx.y * 2 + (warpN >> 1)];
        #pragma unroll
        for (int mi = 0; mi < 4; mi++)
            #pragma unroll
            for (int ni = 0; ni < 4; ni++) {
                acc[mi][ni][0] = (acc[mi][ni][0] + bc0[ni]) * invt;
                acc[mi][ni][1] = (acc[mi][ni][1] + bc1[ni]) * invt;
                acc[mi][ni][2] = (acc[mi][ni][2] + bc0[ni]) * invt;
                acc[mi][ni][3] = (acc[mi][ni][3] + bc1[ni]) * invt;
            }
        // per-(row, warp) max over this warp's 32 cols
        #pragma unroll
        for (int mi = 0; mi < 4; mi++)
            #pragma unroll
            for (int rh = 0; rh < 2; rh++) {
                float m = -1e30f;
                #pragma unroll
                for (int ni = 0; ni < 4; ni++) {
                    m = fmaxf(m, acc[mi][ni][rh * 2]);
                    m = fmaxf(m, acc[mi][ni][rh * 2 + 1]);
                }
                m = fmaxf(m, __shfl_xor_sync(0xffffffffu, m, 1));
                m = fmaxf(m, __shfl_xor_sync(0xffffffffu, m, 2));
                red[0][warpN][warpM * 64 + mi * 16 + rh * 8 + (lane >> 2)] = m;
            }
        __syncthreads();
        const int wb = warpN & 2;
        #pragma unroll
        for (int mi = 0; mi < 4; mi++)
            #pragma unroll
            for (int rh = 0; rh < 2; rh++) {
                int row = warpM * 64 + mi * 16 + rh * 8 + (lane >> 2);
                float M2 = fmaxf(red[0][wb][row], red[0][wb + 1][row]);
                float s = 0.f;
                #pragma unroll
                for (int ni = 0; ni < 4; ni++) {
                    float e0 = __expf(acc[mi][ni][rh * 2] - M2);
                    float e1 = __expf(acc[mi][ni][rh * 2 + 1] - M2);
                    acc[mi][ni][rh * 2] = e0; acc[mi][ni][rh * 2 + 1] = e1;
                    s += e0 + e1;
                }
                s += __shfl_xor_sync(0xffffffffu, s, 1);
                s += __shfl_xor_sync(0xffffffffu, s, 2);
                red[1][warpN][row] = s;
            }
        __syncthreads();
        #pragma unroll
        for (int mi = 0; mi < 4; mi++)
            #pragma unroll
            for (int rh = 0; rh < 2; rh++) {
                int rloc = warpM * 64 + mi * 16 + rh * 8 + (lane >> 2);
                long row = rowBase + rloc;
                float inv = 1.0f / (red[1][wb][rloc] + red[1][wb + 1][rloc]);
                #pragma unroll
                for (int ni = 0; ni < 4; ni++) {
                    int col = colBase + warpN * 32 + ni * 8 + (lane & 3) * 2;
                    float v0 = acc[mi][ni][rh * 2] * inv;
                    float v1 = acc[mi][ni][rh * 2 + 1] * inv;
                    bf16 h0, l0, h1, l1;
                    split1(v0, h0, l0); split1(v1, h1, l1);
                    *reinterpret_cast<__nv_bfloat162*>(Chi + row * N + col) = __nv_bfloat162(h0, h1);
                    *reinterpret_cast<__nv_bfloat162*>(Clo + row * N + col) = __nv_bfloat162(l0, l1);
                }
            }
    } else {
        #pragma unroll
        for (int mi = 0; mi < 4; mi++)
            #pragma unroll
            for (int ni = 0; ni < 4; ni++) {
                int col = colBase + warpN * 32 + ni * 8 + (lane & 3) * 2;
                #pragma unroll
                for (int rh = 0; rh < 2; rh++) {
                    long row = rowBase + warpM * 64 + mi * 16 + rh * 8 + (lane >> 2);
                    float v0 = acc[mi][ni][rh * 2] + bc0[ni];
                    float v1 = acc[mi][ni][rh * 2 + 1] + bc1[ni];
                    if (OUT_PAIR) {
                        bf16 h0, l0, h1, l1;
                        split1(v0, h0, l0); split1(v1, h1, l1);
                        *reinterpret_cast<__nv_bfloat162*>(Chi + row * N + col) = __nv_bfloat162(h0, h1);
                        *reinterpret_cast<__nv_bfloat162*>(Clo + row * N + col) = __nv_bfloat162(l0, l1);
                    } else {
                        float2 o; o.x = v0; o.y = v1;
                        *reinterpret_cast<float2*>(C + row * N + col) = o;
                    }
                }
            }
    }
}

// ---------------- pooling: per (b,h,split): partial st = sw^T @ fx [64x64], + col sums
__global__ __launch_bounds__(256) void pool_k()
{
    const int s = blockIdx.x;
    const int bh = blockIdx.y;
    const int b = bh >> 3, h = bh & 7;
    const int tid = threadIdx.x;
    const int cx = tid & 15, gy = tid >> 4;
    __shared__ float Ss[16][64];
    __shared__ float Sf[16][64];
    float acc[4][4] = {};
    float sn = 0.f;
    const int chunk = NPTS / SPLITS;  // 1024
    const long base = (long)b * NPTS * INNER_ + h * 64;
    const int r = tid >> 4, g4 = (tid & 15) << 2;

    for (int n0 = s * chunk; n0 < (s + 1) * chunk; n0 += 16) {
        long addr = base + (long)(n0 + r) * INNER_ + g4;
        *reinterpret_cast<float4*>(&Ss[r][g4]) = loadpair4(g_swHi, g_swLo, addr);
        *reinterpret_cast<float4*>(&Sf[r][g4]) = loadpair4(g_fxHi, g_fxLo, addr);
        __syncthreads();
        #pragma unroll
        for (int kk = 0; kk < 16; kk++) {
            float4 a4 = *reinterpret_cast<const float4*>(&Ss[kk][gy << 2]);
            float4 b4 = *reinterpret_cast<const float4*>(&Sf[kk][cx << 2]);
            float a[4] = {a4.x, a4.y, a4.z, a4.w};
            float bb[4] = {b4.x, b4.y, b4.z, b4.w};
            #pragma unroll
            for (int i = 0; i < 4; i++)
                #pragma unroll
                for (int j = 0; j < 4; j++)
                    acc[i][j] += a[i] * bb[j];
        }
        if (tid < 64) {
            #pragma unroll
            for (int kk = 0; kk < 16; kk++) sn += Ss[kk][tid];
        }
        __syncthreads();
    }
    long pbase = ((long)bh * SPLITS + s) * 4096;
    #pragma unroll
    for (int i = 0; i < 4; i++)
        #pragma unroll
        for (int j = 0; j < 4; j++)
            g_part[pbase + (gy * 4 + i) * 64 + cx * 4 + j] = acc[i][j];
    if (tid < 64) g_psn[((long)bh * SPLITS + s) * 64 + tid] = sn;
}

// ---------------- deterministic split reduce + snorm divide -> st[b,h,g,d]
__global__ __launch_bounds__(256) void reduce_k()
{
    const int bh = blockIdx.x;
    const int tid = threadIdx.x;
    __shared__ float inv_sn[64];
    if (tid < 64) {
        float s = 0.f;
        #pragma unroll
        for (int sp = 0; sp < SPLITS; sp++)
            s += g_psn[((long)bh * SPLITS + sp) * 64 + tid];
        inv_sn[tid] = 1.0f / (s + 1e-5f);
    }
    __syncthreads();
    for (int e = tid; e < 4096; e += 256) {
        float s = 0.f;
        #pragma unroll
        for (int sp = 0; sp < SPLITS; sp++)
            s += g_part[((long)bh * SPLITS + sp) * 4096 + e];
        g_st[(long)bh * 4096 + e] = s * inv_sn[e >> 6];
    }
}

// ---------------- kv = mean_h st; k=kv@Wk^T (row-normalized); v=kv@Wv^T
__global__ __launch_bounds__(256) void kv_k(
    const float* __restrict__ Wk, const float* __restrict__ Wv)
{
    __shared__ float kv[4096];
    __shared__ float kb[4096];
    __shared__ float rn[64];
    const int b = blockIdx.x;
    const int tid = threadIdx.x;
    for (int e = tid; e < 4096; e += 256) {
        float s = 0.f;
        #pragma unroll
        for (int h = 0; h < 8; h++) s += g_st[(long)(b * 8 + h) * 4096 + e];
        kv[e] = s * 0.125f;
    }
    __syncthreads();
    {
        const int d = tid & 63;
        const float4* wkp = reinterpret_cast<const float4*>(Wk + d * 64);
        const float4* wvp = reinterpret_cast<const float4*>(Wv + d * 64);
        #pragma unroll
        for (int k = 0; k < 16; k++) {
            int g = (tid >> 6) + k * 4;
            const float4* kvp = reinterpret_cast<const float4*>(kv + g * 64);
            float sk = 0.f, sv = 0.f;
            #pragma unroll
            for (int e4 = 0; e4 < 16; e4++) {
                float4 x = kvp[e4];
                float4 wk4 = wkp[e4], wv4 = wvp[e4];
                sk += x.x * wk4.x + x.y * wk4.y + x.z * wk4.z + x.w * wk4.w;
                sv += x.x * wv4.x + x.y * wv4.y + x.z * wv4.z + x.w * wv4.w;
            }
            kb[g * 64 + d] = sk;
            g_v[(long)b * 4096 + g * 64 + d] = sv;
        }
    }
    __syncthreads();
    if (tid < 64) {
        float s = 0.f;
        for (int d = 0; d < 64; d++) { float x = kb[tid * 64 + d]; s += x * x; }
        rn[tid] = 1.0f / fmaxf(sqrtf(s), 1e-12f);
    }
    __syncthreads();
    for (int e = tid; e < 4096; e += 256)
        g_kn[(long)b * 4096 + e] = kb[e] * rn[e >> 6];
}

// ---------------- per (b,h): slice-token attention + residual + fold Wout ->
// M[b][c][h*64+g] ( [N][K] layout for the final mma gemm )
__global__ __launch_bounds__(256) void attn_k(
    const float* __restrict__ Wq, const float* __restrict__ Wout,
    const float* __restrict__ attn_scale, const float* __restrict__ res_scale)
{
    extern __shared__ float sm[];
    float* sst = sm;            // [64][64] st, later out_st
    float* sq  = sm + 4096;     // [64][64] q/qn, later v
    float* sc  = sm + 8192;     // [64][65] scores
    const int bh = blockIdx.x;
    const int b = bh >> 3, h = bh & 7;
    const int tid = threadIdx.x;

    for (int e = tid; e < 4096; e += 256) sst[e] = g_st[(long)bh * 4096 + e];
    __syncthreads();

    {   // q = st @ Wq^T
        const int d = tid & 63;
        const float4* wp = reinterpret_cast<const float4*>(Wq + d * 64);
        #pragma unroll
        for (int k = 0; k < 16; k++) {
            int g = (tid >> 6) + k * 4;
            const float4* sp = reinterpret_cast<const float4*>(sst + g * 64);
            float s = 0.f;
            #pragma unroll
            for (int e4 = 0; e4 < 16; e4++) {
                float4 w = wp[e4], x = sp[e4];
                s += w.x * x.x + w.y * x.y + w.z * x.z + w.w * x.w;
            }
            sq[g * 64 + d] = s;
        }
    }
    __syncthreads();
    if (tid < 64) {   // normalize q rows in place
        float s = 0.f;
        for (int d = 0; d < 64; d++) { float x = sq[tid * 64 + d]; s += x * x; }
        float inv = 1.0f / fmaxf(sqrtf(s), 1e-12f);
        for (int d = 0; d < 64; d++) sq[tid * 64 + d] *= inv;
    }
    __syncthreads();
    {   // scores = qn @ kn^T * attn_scale
        const float asc = attn_scale[h];
        const int ss = tid & 63;
        const float4* kp = reinterpret_cast<const float4*>(g_kn + (long)b * 4096 + ss * 64);
        #pragma unroll
        for (int k = 0; k < 16; k++) {
            int g = (tid >> 6) + k * 4;
            const float4* qp = reinterpret_cast<const float4*>(sq + g * 64);
            float s = 0.f;
            #pragma unroll
            for (int d4 = 0; d4 < 16; d4++) {
                float4 kk = kp[d4], qq = qp[d4];
                s += kk.x * qq.x + kk.y * qq.y + kk.z * qq.z + kk.w * qq.w;
            }
            sc[g * 65 + ss] = s * asc;
        }
    }
    __syncthreads();
    if (tid < 64) {   // row softmax over 64 slice tokens
        float m = -1e30f;
        for (int s = 0; s < 64; s++) m = fmaxf(m, sc[tid * 65 + s]);
        float sum = 0.f;
        for (int s = 0; s < 64; s++) {
            float e = __expf(sc[tid * 65 + s] - m);
            sc[tid * 65 + s] = e; sum += e;
        }
        float inv = 1.0f / sum;
        for (int s = 0; s < 64; s++) sc[tid * 65 + s] *= inv;
    }
    // overlap: load v into sq (qn is dead)
    for (int e = tid; e < 4096; e += 256) sq[e] = g_v[(long)b * 4096 + e];
    __syncthreads();

    const float res = *res_scale;
    float outreg[16];
    {   // out_st = attn @ v + res*st
        const int d = tid & 63;
        #pragma unroll
        for (int k = 0; k < 16; k++) {
            int g = (tid >> 6) + k * 4;
            float s = 0.f;
            #pragma unroll 16
            for (int ss = 0; ss < 64; ss++)
                s += sc[g * 65 + ss] * sq[ss * 64 + d];
            outreg[k] = s + res * sst[g * 64 + d];
        }
    }
    __syncthreads();
    {   // write out_st into sst
        const int d = tid & 63;
        #pragma unroll
        for (int k = 0; k < 16; k++)
            sst[((tid >> 6) + k * 4) * 64 + d] = outreg[k];
    }
    __syncthreads();
    {   // M[b][c][h*64+g] = sum_d out_st[g,d] * Wout[c, h*64+d]
        const int c = tid;   // 0..255
        const float4* wp = reinterpret_cast<const float4*>(Wout + c * INNER_ + h * 64);
        for (int g = 0; g < 64; g++) {
            const float4* op = reinterpret_cast<const float4*>(sst + g * 64);
            float s = 0.f;
            #pragma unroll
            for (int d4 = 0; d4 < 16; d4++) {
                float4 w = wp[d4], o = op[d4];
                s += w.x * o.x + w.y * o.y + w.z * o.z + w.w * o.w;
            }
            g_M[((long)b * DIM_ + c) * INNER_ + h * 64 + g] = s;
        }
    }
}

// ---------------- split M into bf16 hi/lo planes ----------------
__global__ __launch_bounds__(256) void splitM_k()
{
    int i = blockIdx.x * 256 + threadIdx.x;   // total B_*DIM_*INNER_ = 524288
    split1(g_M[i], g_MHi[i], g_MLo[i]);
}

// ---------------- host launcher ----------------
extern "C" void kernel_launch(void* const* d_in, const int* in_sizes, int n_in,
                              void* d_out, int out_size)
{
    const float* x         = (const float*)d_in[0];
    const float* Wfx       = (const float*)d_in[1];
    const float* bfx       = (const float*)d_in[2];
    const float* Wx        = (const float*)d_in[3];
    const float* bx        = (const float*)d_in[4];
    const float* Wslice    = (const float*)d_in[5];
    const float* bslice    = (const float*)d_in[6];
    const float* temp      = (const float*)d_in[7];
    const float* Wq        = (const float*)d_in[8];
    const float* Wk        = (const float*)d_in[9];
    const float* Wv        = (const float*)d_in[10];
    const float* res_scale = (const float*)d_in[11];
    const float* attn_scl  = (const float*)d_in[12];
    const float* Wout      = (const float*)d_in[13];
    const float* bout      = (const float*)d_in[14];
    float* out = (float*)d_out;

    bf16 *p_fxHi, *p_fxLo, *p_swHi, *p_swLo;
    bf16 *p_WfxHi, *p_WfxLo, *p_WcHi, *p_WcLo, *p_MHi, *p_MLo;
    float *p_lbias;
    cudaGetSymbolAddress((void**)&p_fxHi, g_fxHi);
    cudaGetSymbolAddress((void**)&p_fxLo, g_fxLo);
    cudaGetSymbolAddress((void**)&p_swHi, g_swHi);
    cudaGetSymbolAddress((void**)&p_swLo, g_swLo);
    cudaGetSymbolAddress((void**)&p_WfxHi, g_WfxHi);
    cudaGetSymbolAddress((void**)&p_WfxLo, g_WfxLo);
    cudaGetSymbolAddress((void**)&p_WcHi, g_WcombHi);
    cudaGetSymbolAddress((void**)&p_WcLo, g_WcombLo);
    cudaGetSymbolAddress((void**)&p_MHi, g_MHi);
    cudaGetSymbolAddress((void**)&p_MLo, g_MLo);
    cudaGetSymbolAddress((void**)&p_lbias, g_lbias);

    cudaFuncSetAttribute(attn_k, cudaFuncAttributeMaxDynamicSharedMemorySize, 49408);

    prep_k<<<512, 256>>>(Wfx, Wx, Wslice, bx, bslice);

    // fx = x @ Wfx^T + bfx  ->  bf16 hi/lo planes
    mma_gemm<true, false, true><<<dim3(1024, 4, 1), 256>>>(
        x, nullptr, nullptr, p_WfxHi, p_WfxLo, bfx, nullptr,
        nullptr, p_fxHi, p_fxLo, INNER_, DIM_, 0, 0, 0);

    // sw = softmax_G((x @ Wcomb^T + lbias) / temp[h])  ->  bf16 hi/lo planes
    mma_gemm<true, true, true><<<dim3(1024, 4, 1), 256>>>(
        x, nullptr, nullptr, p_WcHi, p_WcLo, p_lbias, temp,
        nullptr, p_swHi, p_swLo, INNER_, DIM_, 0, 0, 0);

    pool_k<<<dim3(SPLITS, BH_), 256>>>();
    reduce_k<<<BH_, 256>>>();
    kv_k<<<B_, 256>>>(Wk, Wv);
    attn_k<<<BH_, 256, 49408>>>(Wq, Wout, attn_scl, res_scale);
    splitM_k<<<2048, 256>>>();

    // out = sw @ M[b]^T + bout  (M stored [N][K]; scatter + Wout folded)
    mma_gemm<false, false, false><<<dim3(256, 2, B_), 256>>>(
        nullptr, p_swHi, p_swLo, p_MHi, p_MLo, bout, nullptr,
        out, nullptr, nullptr, DIM_, INNER_,
        (long)NPTS * INNER_, (long)DIM_ * INNER_, (long)NPTS * DIM_);
}

// round 6
// speedup vs baseline: 2.3770x; 1.4942x over previous
#include <cuda_runtime.h>
#include <cuda_bf16.h>
#include <math.h>
#include <stdint.h>

#define H_ 8
#define D_ 64
#define G_ 64
#define DIM_ 256
#define INNER_ 512
#define B_ 4
#define NPTS 32768
#define BH_ (B_*H_)
#define PSPLITS 16
#define LDA 40    // smem row stride for [row][k32] tiles (80B, 16B-aligned, conflict-free)
#define LDT 136   // smem row stride for [k32][col128] trans tiles (272B)

using bf16 = __nv_bfloat16;

// ---------------- scratch (static device allocations; no cudaMalloc) ----------------
__device__ bf16 g_xHi[(size_t)B_ * NPTS * DIM_];
__device__ bf16 g_xLo[(size_t)B_ * NPTS * DIM_];
__device__ bf16 g_swHi[(size_t)B_ * NPTS * INNER_];
__device__ bf16 g_swLo[(size_t)B_ * NPTS * INNER_];
__device__ bf16 g_WcombHi[INNER_ * DIM_];
__device__ bf16 g_WcombLo[INNER_ * DIM_];
__device__ float g_lbias[INNER_];
__device__ float g_Ppart[(size_t)B_ * PSPLITS * INNER_ * DIM_];   // 33.5 MB
__device__ float g_psn[(size_t)B_ * PSPLITS * INNER_];
__device__ float g_st[(size_t)BH_ * G_ * D_];
__device__ float g_kn[(size_t)B_ * G_ * D_];
__device__ float g_v[(size_t)B_ * G_ * D_];
__device__ float g_M[(size_t)B_ * DIM_ * INNER_];     // [b][c][inner]
__device__ bf16 g_MHi[(size_t)B_ * DIM_ * INNER_];
__device__ bf16 g_MLo[(size_t)B_ * DIM_ * INNER_];

// ---------------- helpers ----------------
__device__ __forceinline__ void split1(float v, bf16& h, bf16& l) {
    h = __float2bfloat16(v);
    l = __float2bfloat16(v - __bfloat162float(h));
}
__device__ __forceinline__ uint32_t sptr(const void* p) {
    return (uint32_t)__cvta_generic_to_shared(p);
}
__device__ __forceinline__ void ldsm4(uint32_t* r, uint32_t addr) {
    asm volatile("ldmatrix.sync.aligned.m8n8.x4.shared.b16 {%0,%1,%2,%3}, [%4];"
                 : "=r"(r[0]), "=r"(r[1]), "=r"(r[2]), "=r"(r[3]) : "r"(addr));
}
__device__ __forceinline__ void ldsm4t(uint32_t* r, uint32_t addr) {
    asm volatile("ldmatrix.sync.aligned.m8n8.x4.trans.shared.b16 {%0,%1,%2,%3}, [%4];"
                 : "=r"(r[0]), "=r"(r[1]), "=r"(r[2]), "=r"(r[3]) : "r"(addr));
}
__device__ __forceinline__ void mma16816(float* d, const uint32_t* a, const uint32_t* b) {
    asm volatile("mma.sync.aligned.m16n8k16.row.col.f32.bf16.bf16.f32 "
                 "{%0,%1,%2,%3}, {%4,%5,%6,%7}, {%8,%9}, {%0,%1,%2,%3};"
                 : "+f"(d[0]), "+f"(d[1]), "+f"(d[2]), "+f"(d[3])
                 : "r"(a[0]), "r"(a[1]), "r"(a[2]), "r"(a[3]), "r"(b[0]), "r"(b[1]));
}
__device__ __forceinline__ void cp16(bf16* s, const bf16* g) {
    asm volatile("cp.async.cg.shared.global [%0], [%1], 16;"
                 :: "r"(sptr(s)), "l"(g));
}
__device__ __forceinline__ void cp_commit() {
    asm volatile("cp.async.commit_group;");
}
template<int NN> __device__ __forceinline__ void cp_wait() {
    asm volatile("cp.async.wait_group %0;" :: "n"(NN));
}

// ---------------- split x into bf16 hi/lo planes ----------------
__global__ __launch_bounds__(256) void splitX_k(const float* __restrict__ x)
{
    long i = (long)blockIdx.x * 256 + threadIdx.x;      // float4 index
    float4 v = reinterpret_cast<const float4*>(x)[i];
    bf16 h0,l0,h1,l1,h2,l2,h3,l3;
    split1(v.x,h0,l0); split1(v.y,h1,l1); split1(v.z,h2,l2); split1(v.w,h3,l3);
    __nv_bfloat162 ph0(h0,h1), ph1(h2,h3), pl0(l0,l1), pl1(l2,l3);
    uint2 uh, ul;
    uh.x = *reinterpret_cast<uint32_t*>(&ph0); uh.y = *reinterpret_cast<uint32_t*>(&ph1);
    ul.x = *reinterpret_cast<uint32_t*>(&pl0); ul.y = *reinterpret_cast<uint32_t*>(&pl1);
    reinterpret_cast<uint2*>(g_xHi)[i] = uh;
    reinterpret_cast<uint2*>(g_xLo)[i] = ul;
}

// ---------------- prep: fold Wslice into Wx -> Wcomb [N][K] split; logit bias ----
__global__ __launch_bounds__(256) void prep_k(
    const float* __restrict__ Wx, const float* __restrict__ Wslice,
    const float* __restrict__ bx, const float* __restrict__ bslice)
{
    int idx = blockIdx.x * 256 + threadIdx.x;       // 0 .. 131071
    int n = idx >> 8;                               // output col (h*64+g)
    int k = idx & 255;                              // input dim
    int h = n >> 6, g = n & 63;
    float s = 0.f;
    #pragma unroll 16
    for (int d = 0; d < 64; d++)
        s += Wslice[g * 64 + d] * Wx[(h * 64 + d) * DIM_ + k];
    split1(s, g_WcombHi[idx], g_WcombLo[idx]);
    if (k == 0) {
        float sb = 0.f;
        for (int d = 0; d < 64; d++) sb += Wslice[g * 64 + d] * bx[h * 64 + d];
        g_lbias[n] = sb + bslice[g];
    }
}

// ---------------- pipelined tensor-core GEMM: C[M,N] = A[M,K] @ B^T (B [N][K])
// split-bf16 3-term, cp.async 2-stage. 128x128 tile, 8 warps (2x4), warp 64x32.
template<bool SOFTMAX, bool OUT_PAIR>
__global__ __launch_bounds__(256) void mma_gemm(
    const bf16* __restrict__ Ahi, const bf16* __restrict__ Alo,
    const bf16* __restrict__ Bhi, const bf16* __restrict__ Blo,
    const float* __restrict__ bias, const float* __restrict__ temp,
    float* __restrict__ C, bf16* __restrict__ Chi, bf16* __restrict__ Clo,
    int N, int K, long sA, long sB, long sC)
{
    extern __shared__ bf16 smem[];
    __shared__ float red[2][4][128];
    const int STG = 128 * LDA;          // elems per plane

    const int tid = threadIdx.x;
    const int lane = tid & 31, wid = tid >> 5;
    const int warpM = wid & 1, warpN = wid >> 1;
    const long rowBase = (long)blockIdx.x * 128;
    const int colBase = blockIdx.y * 128;

    Ahi += (long)blockIdx.z * sA; Alo += (long)blockIdx.z * sA;
    Bhi += (long)blockIdx.z * sB; Blo += (long)blockIdx.z * sB;
    if (OUT_PAIR) { Chi += (long)blockIdx.z * sC; Clo += (long)blockIdx.z * sC; }
    else          { C += (long)blockIdx.z * sC; }

    float acc[4][4][4] = {};
    const int NK = K / 32;

    auto load = [&](int st, int kt) {
        bf16* s = smem + st * 4 * STG;
        const long ko = (long)kt * 32;
        #pragma unroll
        for (int l = 0; l < 2; l++) {
            int f = l * 256 + tid;
            int r = f >> 2, c8 = (f & 3) * 8;
            cp16(s + r * LDA + c8,           Ahi + (rowBase + r) * K + ko + c8);
            cp16(s + STG + r * LDA + c8,     Alo + (rowBase + r) * K + ko + c8);
            cp16(s + 2*STG + r * LDA + c8,   Bhi + (long)(colBase + r) * K + ko + c8);
            cp16(s + 3*STG + r * LDA + c8,   Blo + (long)(colBase + r) * K + ko + c8);
        }
    };

    load(0, 0); cp_commit();
    for (int kt = 0; kt < NK; kt++) {
        if (kt + 1 < NK) { load((kt + 1) & 1, kt + 1); cp_commit(); cp_wait<1>(); }
        else             { cp_wait<0>(); }
        __syncthreads();
        const bf16* s = smem + (kt & 1) * 4 * STG;
        #pragma unroll
        for (int kh = 0; kh < 2; kh++) {
            uint32_t ah[4][4], al[4][4], bh[4][2], bl[4][2];
            #pragma unroll
            for (int mi = 0; mi < 4; mi++) {
                int rrow = warpM * 64 + mi * 16 + (lane & 15);
                int ccol = kh * 16 + ((lane >> 4) << 3);
                ldsm4(ah[mi], sptr(s + rrow * LDA + ccol));
                ldsm4(al[mi], sptr(s + STG + rrow * LDA + ccol));
            }
            #pragma unroll
            for (int p = 0; p < 2; p++) {
                int nrow = warpN * 32 + p * 16 + ((lane & 7) | (((lane >> 4) & 1) << 3));
                int ccol = kh * 16 + (((lane >> 3) & 1) << 3);
                uint32_t t[4];
                ldsm4(t, sptr(s + 2*STG + nrow * LDA + ccol));
                bh[2*p][0] = t[0]; bh[2*p][1] = t[1];
                bh[2*p+1][0] = t[2]; bh[2*p+1][1] = t[3];
                ldsm4(t, sptr(s + 3*STG + nrow * LDA + ccol));
                bl[2*p][0] = t[0]; bl[2*p][1] = t[1];
                bl[2*p+1][0] = t[2]; bl[2*p+1][1] = t[3];
            }
            #pragma unroll
            for (int mi = 0; mi < 4; mi++)
                #pragma unroll
                for (int ni = 0; ni < 4; ni++) {
                    mma16816(acc[mi][ni], ah[mi], bh[ni]);
                    mma16816(acc[mi][ni], ah[mi], bl[ni]);
                    mma16816(acc[mi][ni], al[mi], bh[ni]);
                }
        }
        __syncthreads();
    }

    // ---- epilogue ----
    float bc0[4], bc1[4];
    #pragma unroll
    for (int ni = 0; ni < 4; ni++) {
        int col = colBase + warpN * 32 + ni * 8 + (lane & 3) * 2;
        bc0[ni] = bias[col]; bc1[ni] = bias[col + 1];
    }

    if (SOFTMAX) {
        const float invt = 1.0f / temp[blockIdx.y * 2 + (warpN >> 1)];
        #pragma unroll
        for (int mi = 0; mi < 4; mi++)
            #pragma unroll
            for (int ni = 0; ni < 4; ni++) {
                acc[mi][ni][0] = (acc[mi][ni][0] + bc0[ni]) * invt;
                acc[mi][ni][1] = (acc[mi][ni][1] + bc1[ni]) * invt;
                acc[mi][ni][2] = (acc[mi][ni][2] + bc0[ni]) * invt;
                acc[mi][ni][3] = (acc[mi][ni][3] + bc1[ni]) * invt;
            }
        #pragma unroll
        for (int mi = 0; mi < 4; mi++)
            #pragma unroll
            for (int rh = 0; rh < 2; rh++) {
                float m = -1e30f;
                #pragma unroll
                for (int ni = 0; ni < 4; ni++) {
                    m = fmaxf(m, acc[mi][ni][rh * 2]);
                    m = fmaxf(m, acc[mi][ni][rh * 2 + 1]);
                }
                m = fmaxf(m, __shfl_xor_sync(0xffffffffu, m, 1));
                m = fmaxf(m, __shfl_xor_sync(0xffffffffu, m, 2));
                red[0][warpN][warpM * 64 + mi * 16 + rh * 8 + (lane >> 2)] = m;
            }
        __syncthreads();
        const int wb = warpN & 2;
        #pragma unroll
        for (int mi = 0; mi < 4; mi++)
            #pragma unroll
            for (int rh = 0; rh < 2; rh++) {
                int row = warpM * 64 + mi * 16 + rh * 8 + (lane >> 2);
                float M2 = fmaxf(red[0][wb][row], red[0][wb + 1][row]);
                float ssum = 0.f;
                #pragma unroll
                for (int ni = 0; ni < 4; ni++) {
                    float e0 = __expf(acc[mi][ni][rh * 2] - M2);
                    float e1 = __expf(acc[mi][ni][rh * 2 + 1] - M2);
                    acc[mi][ni][rh * 2] = e0; acc[mi][ni][rh * 2 + 1] = e1;
                    ssum += e0 + e1;
                }
                ssum += __shfl_xor_sync(0xffffffffu, ssum, 1);
                ssum += __shfl_xor_sync(0xffffffffu, ssum, 2);
                red[1][warpN][row] = ssum;
            }
        __syncthreads();
        #pragma unroll
        for (int mi = 0; mi < 4; mi++)
            #pragma unroll
            for (int rh = 0; rh < 2; rh++) {
                int rloc = warpM * 64 + mi * 16 + rh * 8 + (lane >> 2);
                long row = rowBase + rloc;
                float inv = 1.0f / (red[1][wb][rloc] + red[1][wb + 1][rloc]);
                #pragma unroll
                for (int ni = 0; ni < 4; ni++) {
                    int col = colBase + warpN * 32 + ni * 8 + (lane & 3) * 2;
                    float v0 = acc[mi][ni][rh * 2] * inv;
                    float v1 = acc[mi][ni][rh * 2 + 1] * inv;
                    bf16 h0, l0, h1, l1;
                    split1(v0, h0, l0); split1(v1, h1, l1);
                    *reinterpret_cast<__nv_bfloat162*>(Chi + row * N + col) = __nv_bfloat162(h0, h1);
                    *reinterpret_cast<__nv_bfloat162*>(Clo + row * N + col) = __nv_bfloat162(l0, l1);
                }
            }
    } else {
        #pragma unroll
        for (int mi = 0; mi < 4; mi++)
            #pragma unroll
            for (int ni = 0; ni < 4; ni++) {
                int col = colBase + warpN * 32 + ni * 8 + (lane & 3) * 2;
                #pragma unroll
                for (int rh = 0; rh < 2; rh++) {
                    long row = rowBase + warpM * 64 + mi * 16 + rh * 8 + (lane >> 2);
                    float v0 = acc[mi][ni][rh * 2] + bc0[ni];
                    float v1 = acc[mi][ni][rh * 2 + 1] + bc1[ni];
                    if (OUT_PAIR) {
                        bf16 h0, l0, h1, l1;
                        split1(v0, h0, l0); split1(v1, h1, l1);
                        *reinterpret_cast<__nv_bfloat162*>(Chi + row * N + col) = __nv_bfloat162(h0, h1);
                        *reinterpret_cast<__nv_bfloat162*>(Clo + row * N + col) = __nv_bfloat162(l0, l1);
                    } else {
                        float2 o; o.x = v0; o.y = v1;
                        *reinterpret_cast<float2*>(C + row * N + col) = o;
                    }
                }
            }
    }
}

// ---------------- P GEMM (split-K): P[b][inner 512][dim 256] = sw[b]^T @ X[b]
// both operands K(=n)-major in memory -> trans ldmatrix. snorm via ones-mma.
__global__ __launch_bounds__(256) void pgemm_k()
{
    extern __shared__ bf16 smem[];
    const int STG = 32 * LDT;

    const int tid = threadIdx.x;
    const int lane = tid & 31, wid = tid >> 5;
    const int warpM = wid & 1, warpN = wid >> 1;
    const int mBase = blockIdx.x * 128;     // inner
    const int nBase = blockIdx.y * 128;     // dim
    const int z = blockIdx.z, b = z >> 4, sp = z & 15;
    const long nStart = (long)b * NPTS + sp * (NPTS / PSPLITS);
    const bool doSN = (warpN == 0) && (blockIdx.y == 0);

    float acc[4][4][4] = {};
    float accS[4][4] = {};
    const uint32_t ONES2 = 0x3F803F80u;
    uint32_t bones[2] = {ONES2, ONES2};

    auto load = [&](int st, int it) {
        bf16* s = smem + st * 4 * STG;
        const long g0 = nStart + it * 32;
        #pragma unroll
        for (int l = 0; l < 2; l++) {
            int f = l * 256 + tid;
            int r = f >> 4, c8 = (f & 15) * 8;
            cp16(s + r * LDT + c8,           g_swHi + (g0 + r) * INNER_ + mBase + c8);
            cp16(s + STG + r * LDT + c8,     g_swLo + (g0 + r) * INNER_ + mBase + c8);
            cp16(s + 2*STG + r * LDT + c8,   g_xHi + (g0 + r) * DIM_ + nBase + c8);
            cp16(s + 3*STG + r * LDT + c8,   g_xLo + (g0 + r) * DIM_ + nBase + c8);
        }
    };

    const int NIT = (NPTS / PSPLITS) / 32;   // 64
    load(0, 0); cp_commit();
    for (int it = 0; it < NIT; it++) {
        if (it + 1 < NIT) { load((it + 1) & 1, it + 1); cp_commit(); cp_wait<1>(); }
        else              { cp_wait<0>(); }
        __syncthreads();
        const bf16* s = smem + (it & 1) * 4 * STG;
        #pragma unroll
        for (int kh = 0; kh < 2; kh++) {
            const int g = lane >> 3, l8 = lane & 7;
            uint32_t ah[4][4], al[4][4], bh[4][2], bl[4][2];
            int kA = kh * 16 + ((g >> 1) << 3) + l8;
            int mA = (g & 1) << 3;
            #pragma unroll
            for (int mi = 0; mi < 4; mi++) {
                int mrow = warpM * 64 + mi * 16 + mA;
                ldsm4t(ah[mi], sptr(s + kA * LDT + mrow));
                ldsm4t(al[mi], sptr(s + STG + kA * LDT + mrow));
            }
            int kB = kh * 16 + ((g & 1) << 3) + l8;
            int nB0 = (g >> 1) << 3;
            #pragma unroll
            for (int p = 0; p < 2; p++) {
                int ncol = warpN * 32 + p * 16 + nB0;
                uint32_t t[4];
                ldsm4t(t, sptr(s + 2*STG + kB * LDT + ncol));
                bh[2*p][0] = t[0]; bh[2*p][1] = t[1];
                bh[2*p+1][0] = t[2]; bh[2*p+1][1] = t[3];
                ldsm4t(t, sptr(s + 3*STG + kB * LDT + ncol));
                bl[2*p][0] = t[0]; bl[2*p][1] = t[1];
                bl[2*p+1][0] = t[2]; bl[2*p+1][1] = t[3];
            }
            if (doSN) {
                #pragma unroll
                for (int mi = 0; mi < 4; mi++) {
                    mma16816(accS[mi], ah[mi], bones);
                    mma16816(accS[mi], al[mi], bones);
                }
            }
            #pragma unroll
            for (int mi = 0; mi < 4; mi++)
                #pragma unroll
                for (int ni = 0; ni < 4; ni++) {
                    mma16816(acc[mi][ni], ah[mi], bh[ni]);
                    mma16816(acc[mi][ni], ah[mi], bl[ni]);
                    mma16816(acc[mi][ni], al[mi], bh[ni]);
                }
        }
        __syncthreads();
    }

    float* P = g_Ppart + (long)z * INNER_ * DIM_;
    #pragma unroll
    for (int mi = 0; mi < 4; mi++)
        #pragma unroll
        for (int ni = 0; ni < 4; ni++) {
            int col = nBase + warpN * 32 + ni * 8 + (lane & 3) * 2;
            #pragma unroll
            for (int rh = 0; rh < 2; rh++) {
                int row = mBase + warpM * 64 + mi * 16 + rh * 8 + (lane >> 2);
                float2 o; o.x = acc[mi][ni][rh * 2]; o.y = acc[mi][ni][rh * 2 + 1];
                *reinterpret_cast<float2*>(P + (long)row * DIM_ + col) = o;
            }
        }
    if (doSN && (lane & 3) == 0) {
        #pragma unroll
        for (int mi = 0; mi < 4; mi++) {
            int r0 = mBase + warpM * 64 + mi * 16 + (lane >> 2);
            g_psn[(long)z * INNER_ + r0]     = accS[mi][0];
            g_psn[(long)z * INNER_ + r0 + 8] = accS[mi][2];
        }
    }
}

// ---------------- st_k: reduce P splits + snorm; st = (P Wfx_h^T + snorm*bfx)/snorm
__global__ __launch_bounds__(256) void st_k(
    const float* __restrict__ Wfx, const float* __restrict__ bfx)
{
    extern __shared__ float Ps[];   // [64][257]
    __shared__ float inv_sn[64], sn_s[64];
    const int bh = blockIdx.x, b = bh >> 3, h = bh & 7;
    const int tid = threadIdx.x;

    for (int e = tid; e < 64 * 256; e += 256) {
        int g = e >> 8, c = e & 255;
        float s = 0.f;
        #pragma unroll
        for (int sp = 0; sp < PSPLITS; sp++)
            s += g_Ppart[((long)(b * PSPLITS + sp) * INNER_ + h * 64 + g) * DIM_ + c];
        Ps[g * 257 + c] = s;
    }
    if (tid < 64) {
        float s = 0.f;
        #pragma unroll
        for (int sp = 0; sp < PSPLITS; sp++)
            s += g_psn[(long)(b * PSPLITS + sp) * INNER_ + h * 64 + tid];
        sn_s[tid] = s;
        inv_sn[tid] = 1.0f / (s + 1e-5f);
    }
    __syncthreads();

    const int d = tid & 63, q = tid >> 6;
    const float bfxd = bfx[h * 64 + d];
    const float* wrow = Wfx + (long)(h * 64 + d) * DIM_;
    float acc[16] = {};
    for (int c = 0; c < 256; c++) {
        float w = wrow[c];
        #pragma unroll
        for (int i = 0; i < 16; i++)
            acc[i] += Ps[(q * 16 + i) * 257 + c] * w;
    }
    #pragma unroll
    for (int i = 0; i < 16; i++) {
        int g = q * 16 + i;
        g_st[(long)bh * 4096 + g * 64 + d] = (acc[i] + sn_s[g] * bfxd) * inv_sn[g];
    }
}

// ---------------- kv = mean_h st; k=kv@Wk^T (row-normalized); v=kv@Wv^T
__global__ __launch_bounds__(256) void kv_k(
    const float* __restrict__ Wk, const float* __restrict__ Wv)
{
    __shared__ float kv[4096];
    __shared__ float kb[4096];
    __shared__ float rn[64];
    const int b = blockIdx.x;
    const int tid = threadIdx.x;
    for (int e = tid; e < 4096; e += 256) {
        float s = 0.f;
        #pragma unroll
        for (int h = 0; h < 8; h++) s += g_st[(long)(b * 8 + h) * 4096 + e];
        kv[e] = s * 0.125f;
    }
    __syncthreads();
    {
        const int d = tid & 63;
        const float4* wkp = reinterpret_cast<const float4*>(Wk + d * 64);
        const float4* wvp = reinterpret_cast<const float4*>(Wv + d * 64);
        #pragma unroll
        for (int k = 0; k < 16; k++) {
            int g = (tid >> 6) + k * 4;
            const float4* kvp = reinterpret_cast<const float4*>(kv + g * 64);
            float sk = 0.f, sv = 0.f;
            #pragma unroll
            for (int e4 = 0; e4 < 16; e4++) {
                float4 x = kvp[e4];
                float4 wk4 = wkp[e4], wv4 = wvp[e4];
                sk += x.x * wk4.x + x.y * wk4.y + x.z * wk4.z + x.w * wk4.w;
                sv += x.x * wv4.x + x.y * wv4.y + x.z * wv4.z + x.w * wv4.w;
            }
            kb[g * 64 + d] = sk;
            g_v[(long)b * 4096 + g * 64 + d] = sv;
        }
    }
    __syncthreads();
    if (tid < 64) {
        float s = 0.f;
        for (int d = 0; d < 64; d++) { float x = kb[tid * 64 + d]; s += x * x; }
        rn[tid] = 1.0f / fmaxf(sqrtf(s), 1e-12f);
    }
    __syncthreads();
    for (int e = tid; e < 4096; e += 256)
        g_kn[(long)b * 4096 + e] = kb[e] * rn[e >> 6];
}

// ---------------- per (b,h): slice-token attention + residual + fold Wout ->
// M[b][c][h*64+g]
__global__ __launch_bounds__(256) void attn_k(
    const float* __restrict__ Wq, const float* __restrict__ Wout,
    const float* __restrict__ attn_scale, const float* __restrict__ res_scale)
{
    extern __shared__ float sm[];
    float* sst = sm;
    float* sq  = sm + 4096;
    float* sc  = sm + 8192;
    const int bh = blockIdx.x;
    const int b = bh >> 3, h = bh & 7;
    const int tid = threadIdx.x;

    for (int e = tid; e < 4096; e += 256) sst[e] = g_st[(long)bh * 4096 + e];
    __syncthreads();

    {   // q = st @ Wq^T
        const int d = tid & 63;
        const float4* wp = reinterpret_cast<const float4*>(Wq + d * 64);
        #pragma unroll
        for (int k = 0; k < 16; k++) {
            int g = (tid >> 6) + k * 4;
            const float4* sp = reinterpret_cast<const float4*>(sst + g * 64);
            float s = 0.f;
            #pragma unroll
            for (int e4 = 0; e4 < 16; e4++) {
                float4 w = wp[e4], x = sp[e4];
                s += w.x * x.x + w.y * x.y + w.z * x.z + w.w * x.w;
            }
            sq[g * 64 + d] = s;
        }
    }
    __syncthreads();
    if (tid < 64) {
        float s = 0.f;
        for (int d = 0; d < 64; d++) { float x = sq[tid * 64 + d]; s += x * x; }
        float inv = 1.0f / fmaxf(sqrtf(s), 1e-12f);
        for (int d = 0; d < 64; d++) sq[tid * 64 + d] *= inv;
    }
    __syncthreads();
    {   // scores = qn @ kn^T * attn_scale
        const float asc = attn_scale[h];
        const int ss = tid & 63;
        const float4* kp = reinterpret_cast<const float4*>(g_kn + (long)b * 4096 + ss * 64);
        #pragma unroll
        for (int k = 0; k < 16; k++) {
            int g = (tid >> 6) + k * 4;
            const float4* qp = reinterpret_cast<const float4*>(sq + g * 64);
            float s = 0.f;
            #pragma unroll
            for (int d4 = 0; d4 < 16; d4++) {
                float4 kk = kp[d4], qq = qp[d4];
                s += kk.x * qq.x + kk.y * qq.y + kk.z * qq.z + kk.w * qq.w;
            }
            sc[g * 65 + ss] = s * asc;
        }
    }
    __syncthreads();
    if (tid < 64) {
        float m = -1e30f;
        for (int s = 0; s < 64; s++) m = fmaxf(m, sc[tid * 65 + s]);
        float sum = 0.f;
        for (int s = 0; s < 64; s++) {
            float e = __expf(sc[tid * 65 + s] - m);
            sc[tid * 65 + s] = e; sum += e;
        }
        float inv = 1.0f / sum;
        for (int s = 0; s < 64; s++) sc[tid * 65 + s] *= inv;
    }
    for (int e = tid; e < 4096; e += 256) sq[e] = g_v[(long)b * 4096 + e];
    __syncthreads();

    const float res = *res_scale;
    float outreg[16];
    {
        const int d = tid & 63;
        #pragma unroll
        for (int k = 0; k < 16; k++) {
            int g = (tid >> 6) + k * 4;
            float s = 0.f;
            #pragma unroll 16
            for (int ss = 0; ss < 64; ss++)
                s += sc[g * 65 + ss] * sq[ss * 64 + d];
            outreg[k] = s + res * sst[g * 64 + d];
        }
    }
    __syncthreads();
    {
        const int d = tid & 63;
        #pragma unroll
        for (int k = 0; k < 16; k++)
            sst[((tid >> 6) + k * 4) * 64 + d] = outreg[k];
    }
    __syncthreads();
    {
        const int c = tid;
        const float4* wp = reinterpret_cast<const float4*>(Wout + c * INNER_ + h * 64);
        for (int g = 0; g < 64; g++) {
            const float4* op = reinterpret_cast<const float4*>(sst + g * 64);
            float s = 0.f;
            #pragma unroll
            for (int d4 = 0; d4 < 16; d4++) {
                float4 w = wp[d4], o = op[d4];
                s += w.x * o.x + w.y * o.y + w.z * o.z + w.w * o.w;
            }
            g_M[((long)b * DIM_ + c) * INNER_ + h * 64 + g] = s;
        }
    }
}

// ---------------- split M into bf16 hi/lo planes ----------------
__global__ __launch_bounds__(256) void splitM_k()
{
    int i = blockIdx.x * 256 + threadIdx.x;
    split1(g_M[i], g_MHi[i], g_MLo[i]);
}

// ---------------- host launcher ----------------
extern "C" void kernel_launch(void* const* d_in, const int* in_sizes, int n_in,
                              void* d_out, int out_size)
{
    const float* x         = (const float*)d_in[0];
    const float* Wfx       = (const float*)d_in[1];
    const float* bfx       = (const float*)d_in[2];
    const float* Wx        = (const float*)d_in[3];
    const float* bx        = (const float*)d_in[4];
    const float* Wslice    = (const float*)d_in[5];
    const float* bslice    = (const float*)d_in[6];
    const float* temp      = (const float*)d_in[7];
    const float* Wq        = (const float*)d_in[8];
    const float* Wk        = (const float*)d_in[9];
    const float* Wv        = (const float*)d_in[10];
    const float* res_scale = (const float*)d_in[11];
    const float* attn_scl  = (const float*)d_in[12];
    const float* Wout      = (const float*)d_in[13];
    const float* bout      = (const float*)d_in[14];
    float* out = (float*)d_out;

    bf16 *p_xHi, *p_xLo, *p_swHi, *p_swLo, *p_WcHi, *p_WcLo, *p_MHi, *p_MLo;
    float *p_lbias;
    cudaGetSymbolAddress((void**)&p_xHi, g_xHi);
    cudaGetSymbolAddress((void**)&p_xLo, g_xLo);
    cudaGetSymbolAddress((void**)&p_swHi, g_swHi);
    cudaGetSymbolAddress((void**)&p_swLo, g_swLo);
    cudaGetSymbolAddress((void**)&p_WcHi, g_WcombHi);
    cudaGetSymbolAddress((void**)&p_WcLo, g_WcombLo);
    cudaGetSymbolAddress((void**)&p_MHi, g_MHi);
    cudaGetSymbolAddress((void**)&p_MLo, g_MLo);
    cudaGetSymbolAddress((void**)&p_lbias, g_lbias);

    const int GEMM_SMEM = 2 * 4 * 128 * LDA * (int)sizeof(bf16);   // 81920
    const int P_SMEM    = 2 * 4 * 32 * LDT * (int)sizeof(bf16);    // 69632
    const int ST_SMEM   = 64 * 257 * (int)sizeof(float);           // 65792
    cudaFuncSetAttribute(mma_gemm<true, true>,  cudaFuncAttributeMaxDynamicSharedMemorySize, GEMM_SMEM);
    cudaFuncSetAttribute(mma_gemm<false, false>, cudaFuncAttributeMaxDynamicSharedMemorySize, GEMM_SMEM);
    cudaFuncSetAttribute(pgemm_k, cudaFuncAttributeMaxDynamicSharedMemorySize, P_SMEM);
    cudaFuncSetAttribute(st_k, cudaFuncAttributeMaxDynamicSharedMemorySize, ST_SMEM);
    cudaFuncSetAttribute(attn_k, cudaFuncAttributeMaxDynamicSharedMemorySize, 49408);

    splitX_k<<<(B_ * NPTS * DIM_) / 4 / 256, 256>>>(x);
    prep_k<<<512, 256>>>(Wx, Wslice, bx, bslice);

    // sw = softmax_G((x @ Wcomb^T + lbias)/temp)  ->  bf16 hi/lo planes
    mma_gemm<true, true><<<dim3(1024, 4, 1), 256, GEMM_SMEM>>>(
        p_xHi, p_xLo, p_WcHi, p_WcLo, p_lbias, temp,
        nullptr, p_swHi, p_swLo, INNER_, DIM_, 0, 0, 0);

    // P[b] = sw[b]^T @ X[b]  (split-K, snorm fused)
    pgemm_k<<<dim3(4, 2, B_ * PSPLITS), 256, P_SMEM>>>();

    st_k<<<BH_, 256, ST_SMEM>>>(Wfx, bfx);
    kv_k<<<B_, 256>>>(Wk, Wv);
    attn_k<<<BH_, 256, 49408>>>(Wq, Wout, attn_scl, res_scale);
    splitM_k<<<2048, 256>>>();

    // out = sw @ M[b]^T + bout
    mma_gemm<false, false><<<dim3(256, 2, B_), 256, GEMM_SMEM>>>(
        p_swHi, p_swLo, p_MHi, p_MLo, bout, nullptr,
        out, nullptr, nullptr, DIM_, INNER_,
        (long)NPTS * INNER_, (long)DIM_ * INNER_, (long)NPTS * DIM_);
}

// round 11
// speedup vs baseline: 2.4204x; 1.0183x over previous
#include <cuda_runtime.h>
#include <cuda_bf16.h>
#include <math.h>
#include <stdint.h>

#define H_ 8
#define DIM_ 256
#define INNER_ 512
#define B_ 4
#define NPTS 32768
#define BH_ (B_*H_)
#define PSPLITS 16
#define LDA 40    // mma_gemm smem row stride
#define LDTA 136  // pgemm A trans-tile row stride (k-major, 128 cols + pad)
#define LDTB 72   // pgemm B trans-tile row stride (k-major, 64 cols + pad)

using bf16 = __nv_bfloat16;

__device__ bf16 g_xHi[(size_t)B_ * NPTS * DIM_];
__device__ bf16 g_xLo[(size_t)B_ * NPTS * DIM_];
__device__ bf16 g_swHi[(size_t)B_ * NPTS * INNER_];
__device__ bf16 g_swLo[(size_t)B_ * NPTS * INNER_];
__device__ bf16 g_WcombHi[INNER_ * DIM_];
__device__ bf16 g_WcombLo[INNER_ * DIM_];
__device__ float g_lbias[INNER_];
__device__ float g_Ppart[(size_t)B_ * PSPLITS * INNER_ * DIM_];
__device__ float g_psn[(size_t)B_ * PSPLITS * INNER_];
__device__ float g_st[(size_t)BH_ * 4096];
__device__ float g_kn[(size_t)B_ * 4096];
__device__ float g_v[(size_t)B_ * 4096];
__device__ float g_M[(size_t)B_ * DIM_ * INNER_];
__device__ bf16 g_MHi[(size_t)B_ * DIM_ * INNER_];
__device__ bf16 g_MLo[(size_t)B_ * DIM_ * INNER_];

__device__ __forceinline__ void split1(float v, bf16& h, bf16& l) {
    h = __float2bfloat16(v);
    l = __float2bfloat16(v - __bfloat162float(h));
}
__device__ __forceinline__ uint32_t sptr(const void* p) {
    return (uint32_t)__cvta_generic_to_shared(p);
}
__device__ __forceinline__ void ldsm4(uint32_t* r, uint32_t a) {
    asm volatile("ldmatrix.sync.aligned.m8n8.x4.shared.b16 {%0,%1,%2,%3}, [%4];"
                 : "=r"(r[0]), "=r"(r[1]), "=r"(r[2]), "=r"(r[3]) : "r"(a));
}
__device__ __forceinline__ void ldsm4t(uint32_t* r, uint32_t a) {
    asm volatile("ldmatrix.sync.aligned.m8n8.x4.trans.shared.b16 {%0,%1,%2,%3}, [%4];"
                 : "=r"(r[0]), "=r"(r[1]), "=r"(r[2]), "=r"(r[3]) : "r"(a));
}
__device__ __forceinline__ void mma16816(float* d, const uint32_t* a, const uint32_t* b) {
    asm volatile("mma.sync.aligned.m16n8k16.row.col.f32.bf16.bf16.f32 "
                 "{%0,%1,%2,%3}, {%4,%5,%6,%7}, {%8,%9}, {%0,%1,%2,%3};"
                 : "+f"(d[0]), "+f"(d[1]), "+f"(d[2]), "+f"(d[3])
                 : "r"(a[0]), "r"(a[1]), "r"(a[2]), "r"(a[3]), "r"(b[0]), "r"(b[1]));
}
__device__ __forceinline__ void cp16(bf16* s, const bf16* g) {
    asm volatile("cp.async.cg.shared.global [%0], [%1], 16;" :: "r"(sptr(s)), "l"(g));
}
__device__ __forceinline__ void cp_commit() { asm volatile("cp.async.commit_group;"); }
template<int NN> __device__ __forceinline__ void cp_wait() {
    asm volatile("cp.async.wait_group %0;" :: "n"(NN));
}

__global__ __launch_bounds__(256) void splitX_k(const float* __restrict__ x) {
    long i = (long)blockIdx.x * 256 + threadIdx.x;
    float4 v = reinterpret_cast<const float4*>(x)[i];
    bf16 h0,l0,h1,l1,h2,l2,h3,l3;
    split1(v.x,h0,l0); split1(v.y,h1,l1); split1(v.z,h2,l2); split1(v.w,h3,l3);
    __nv_bfloat162 a(h0,h1), b(h2,h3), c(l0,l1), d(l2,l3);
    reinterpret_cast<uint2*>(g_xHi)[i] = make_uint2(*(uint32_t*)&a, *(uint32_t*)&b);
    reinterpret_cast<uint2*>(g_xLo)[i] = make_uint2(*(uint32_t*)&c, *(uint32_t*)&d);
}

__global__ __launch_bounds__(256) void prep_k(
    const float* __restrict__ Wx, const float* __restrict__ Wslice,
    const float* __restrict__ bx, const float* __restrict__ bslice) {
    int idx = blockIdx.x * 256 + threadIdx.x;
    int n = idx >> 8, k = idx & 255, h = n >> 6, g = n & 63;
    float s = 0.f;
    #pragma unroll 16
    for (int d = 0; d < 64; d++) s += Wslice[g*64+d] * Wx[(h*64+d)*DIM_ + k];
    split1(s, g_WcombHi[idx], g_WcombLo[idx]);
    if (k == 0) {
        float sb = 0.f;
        for (int d = 0; d < 64; d++) sb += Wslice[g*64+d] * bx[h*64+d];
        g_lbias[n] = sb + bslice[g];
    }
}

// ---- HMMA GEMM: C[M,N] = A[M,K] @ B^T (B [N][K]), split-bf16 3-term ----
template<bool SOFTMAX, bool OUT_PAIR>
__global__ __launch_bounds__(256) void mma_gemm(
    const bf16* __restrict__ Ahi, const bf16* __restrict__ Alo,
    const bf16* __restrict__ Bhi, const bf16* __restrict__ Blo,
    const float* __restrict__ bias, const float* __restrict__ temp,
    float* __restrict__ C, bf16* __restrict__ Chi, bf16* __restrict__ Clo,
    int N, int K, long sA, long sB, long sC)
{
    extern __shared__ bf16 smem[];
    __shared__ float red[2][4][128];
    const int STG = 128 * LDA;

    const int tid = threadIdx.x, lane = tid & 31, wid = tid >> 5;
    const int warpM = wid & 1, warpN = wid >> 1;
    const long rowBase = (long)blockIdx.x * 128;
    const int colBase = blockIdx.y * 128;

    Ahi += (long)blockIdx.z * sA; Alo += (long)blockIdx.z * sA;
    Bhi += (long)blockIdx.z * sB; Blo += (long)blockIdx.z * sB;
    if (OUT_PAIR) { Chi += (long)blockIdx.z * sC; Clo += (long)blockIdx.z * sC; }
    else          { C += (long)blockIdx.z * sC; }

    float acc[4][4][4] = {};
    const int NK = K / 32;

    auto load = [&](int st, int kt) {
        bf16* s = smem + st * 4 * STG;
        const long ko = (long)kt * 32;
        #pragma unroll
        for (int l = 0; l < 2; l++) {
            int f = l * 256 + tid, r = f >> 2, c8 = (f & 3) * 8;
            cp16(s + r*LDA + c8,         Ahi + (rowBase + r) * K + ko + c8);
            cp16(s + STG + r*LDA + c8,   Alo + (rowBase + r) * K + ko + c8);
            cp16(s + 2*STG + r*LDA + c8, Bhi + (long)(colBase + r) * K + ko + c8);
            cp16(s + 3*STG + r*LDA + c8, Blo + (long)(colBase + r) * K + ko + c8);
        }
    };

    load(0, 0); cp_commit();
    for (int kt = 0; kt < NK; kt++) {
        if (kt + 1 < NK) { load((kt + 1) & 1, kt + 1); cp_commit(); cp_wait<1>(); }
        else             { cp_wait<0>(); }
        __syncthreads();
        const bf16* s = smem + (kt & 1) * 4 * STG;
        #pragma unroll
        for (int kh = 0; kh < 2; kh++) {
            uint32_t ah[4][4], al[4][4], bh[4][2], bl[4][2];
            #pragma unroll
            for (int mi = 0; mi < 4; mi++) {
                int rrow = warpM*64 + mi*16 + (lane & 15);
                int ccol = kh*16 + ((lane >> 4) << 3);
                ldsm4(ah[mi], sptr(s + rrow*LDA + ccol));
                ldsm4(al[mi], sptr(s + STG + rrow*LDA + ccol));
            }
            #pragma unroll
            for (int p = 0; p < 2; p++) {
                int nrow = warpN*32 + p*16 + ((lane & 7) | (((lane >> 4) & 1) << 3));
                int ccol = kh*16 + (((lane >> 3) & 1) << 3);
                uint32_t t[4];
                ldsm4(t, sptr(s + 2*STG + nrow*LDA + ccol));
                bh[2*p][0]=t[0]; bh[2*p][1]=t[1]; bh[2*p+1][0]=t[2]; bh[2*p+1][1]=t[3];
                ldsm4(t, sptr(s + 3*STG + nrow*LDA + ccol));
                bl[2*p][0]=t[0]; bl[2*p][1]=t[1]; bl[2*p+1][0]=t[2]; bl[2*p+1][1]=t[3];
            }
            #pragma unroll
            for (int mi = 0; mi < 4; mi++)
                #pragma unroll
                for (int ni = 0; ni < 4; ni++) {
                    mma16816(acc[mi][ni], ah[mi], bh[ni]);
                    mma16816(acc[mi][ni], ah[mi], bl[ni]);
                    mma16816(acc[mi][ni], al[mi], bh[ni]);
                }
        }
        __syncthreads();
    }

    float bc0[4], bc1[4];
    #pragma unroll
    for (int ni = 0; ni < 4; ni++) {
        int col = colBase + warpN*32 + ni*8 + (lane & 3)*2;
        bc0[ni] = bias[col]; bc1[ni] = bias[col + 1];
    }

    if (SOFTMAX) {
        const float invt = 1.0f / temp[blockIdx.y * 2 + (warpN >> 1)];
        #pragma unroll
        for (int mi = 0; mi < 4; mi++)
            #pragma unroll
            for (int ni = 0; ni < 4; ni++) {
                acc[mi][ni][0] = (acc[mi][ni][0] + bc0[ni]) * invt;
                acc[mi][ni][1] = (acc[mi][ni][1] + bc1[ni]) * invt;
                acc[mi][ni][2] = (acc[mi][ni][2] + bc0[ni]) * invt;
                acc[mi][ni][3] = (acc[mi][ni][3] + bc1[ni]) * invt;
            }
        #pragma unroll
        for (int mi = 0; mi < 4; mi++)
            #pragma unroll
            for (int rh = 0; rh < 2; rh++) {
                float m = -1e30f;
                #pragma unroll
                for (int ni = 0; ni < 4; ni++) {
                    m = fmaxf(m, acc[mi][ni][rh*2]);
                    m = fmaxf(m, acc[mi][ni][rh*2+1]);
                }
                m = fmaxf(m, __shfl_xor_sync(0xffffffffu, m, 1));
                m = fmaxf(m, __shfl_xor_sync(0xffffffffu, m, 2));
                red[0][warpN][warpM*64 + mi*16 + rh*8 + (lane >> 2)] = m;
            }
        __syncthreads();
        const int wb = warpN & 2;
        #pragma unroll
        for (int mi = 0; mi < 4; mi++)
            #pragma unroll
            for (int rh = 0; rh < 2; rh++) {
                int row = warpM*64 + mi*16 + rh*8 + (lane >> 2);
                float M2 = fmaxf(red[0][wb][row], red[0][wb + 1][row]);
                float ssum = 0.f;
                #pragma unroll
                for (int ni = 0; ni < 4; ni++) {
                    float e0 = __expf(acc[mi][ni][rh*2] - M2);
                    float e1 = __expf(acc[mi][ni][rh*2+1] - M2);
                    acc[mi][ni][rh*2] = e0; acc[mi][ni][rh*2+1] = e1;
                    ssum += e0 + e1;
                }
                ssum += __shfl_xor_sync(0xffffffffu, ssum, 1);
                ssum += __shfl_xor_sync(0xffffffffu, ssum, 2);
                red[1][warpN][row] = ssum;
            }
        __syncthreads();
        #pragma unroll
        for (int mi = 0; mi < 4; mi++)
            #pragma unroll
            for (int rh = 0; rh < 2; rh++) {
                int rloc = warpM*64 + mi*16 + rh*8 + (lane >> 2);
                long row = rowBase + rloc;
                float inv = 1.0f / (red[1][wb][rloc] + red[1][wb + 1][rloc]);
                #pragma unroll
                for (int ni = 0; ni < 4; ni++) {
                    int col = colBase + warpN*32 + ni*8 + (lane & 3)*2;
                    float v0 = acc[mi][ni][rh*2] * inv;
                    float v1 = acc[mi][ni][rh*2+1] * inv;
                    bf16 h0, l0, h1, l1;
                    split1(v0, h0, l0); split1(v1, h1, l1);
                    *reinterpret_cast<__nv_bfloat162*>(Chi + row*N + col) = __nv_bfloat162(h0, h1);
                    *reinterpret_cast<__nv_bfloat162*>(Clo + row*N + col) = __nv_bfloat162(l0, l1);
                }
            }
    } else {
        #pragma unroll
        for (int mi = 0; mi < 4; mi++)
            #pragma unroll
            for (int ni = 0; ni < 4; ni++) {
                int col = colBase + warpN*32 + ni*8 + (lane & 3)*2;
                #pragma unroll
                for (int rh = 0; rh < 2; rh++) {
                    long row = rowBase + warpM*64 + mi*16 + rh*8 + (lane >> 2);
                    float v0 = acc[mi][ni][rh*2] + bc0[ni];
                    float v1 = acc[mi][ni][rh*2+1] + bc1[ni];
                    if (OUT_PAIR) {
                        bf16 h0, l0, h1, l1;
                        split1(v0, h0, l0); split1(v1, h1, l1);
                        *reinterpret_cast<__nv_bfloat162*>(Chi + row*N + col) = __nv_bfloat162(h0, h1);
                        *reinterpret_cast<__nv_bfloat162*>(Clo + row*N + col) = __nv_bfloat162(l0, l1);
                    } else {
                        *reinterpret_cast<float2*>(C + row*N + col) = make_float2(v0, v1);
                    }
                }
            }
    }
}

// ---- P GEMM (split-K, HMMA): P[b][inner][dim] = sw[b]^T @ X[b]; snorm fused ----
// Tile 128(inner) x 64(dim), warps 4(M) x 2(N), warp tile 32x32 -> 32 acc regs,
// 2 blocks/SM (was 1). Lane->fragment mapping identical to validated R6 code.
__global__ __launch_bounds__(256) void pgemm_k()
{
    extern __shared__ bf16 smem[];
    constexpr int APL = 32 * LDTA;            // elems per A plane (4352)
    constexpr int BPL = 32 * LDTB;            // elems per B plane (2304)
    constexpr int STAGE = 2 * APL + 2 * BPL;  // 13312 elems

    const int tid = threadIdx.x, lane = tid & 31, wid = tid >> 5;
    const int warpM = wid & 3, warpN = wid >> 2;
    const int mBase = blockIdx.x * 128, nBase = blockIdx.y * 64;
    const int z = blockIdx.z, b = z >> 4, sp = z & 15;
    const long nStart = (long)b * NPTS + sp * (NPTS / PSPLITS);
    const bool doSN = (warpN == 0) && (blockIdx.y == 0);

    float acc[2][4][4] = {};
    float accS[2][4] = {};
    uint32_t bones[2] = {0x3F803F80u, 0x3F803F80u};

    auto load = [&](int st, int it) {
        bf16* s = smem + st * STAGE;
        const long g0 = nStart + it * 32;
        #pragma unroll
        for (int l = 0; l < 4; l++) {
            int f = l * 256 + tid;            // 0..1023
            int pl = f >> 9;                  // 0 hi / 1 lo
            int r = (f >> 4) & 31, c = (f & 15) * 8;
            const bf16* g = (pl ? g_swLo : g_swHi) + (g0 + r) * INNER_ + mBase + c;
            cp16(s + pl * APL + r * LDTA + c, g);
        }
        #pragma unroll
        for (int l = 0; l < 2; l++) {
            int f = l * 256 + tid;            // 0..511
            int pl = f >> 8;
            int r = (f >> 3) & 31, c = (f & 7) * 8;
            const bf16* g = (pl ? g_xLo : g_xHi) + (g0 + r) * DIM_ + nBase + c;
            cp16(s + 2 * APL + pl * BPL + r * LDTB + c, g);
        }
    };

    const int NIT = (NPTS / PSPLITS) / 32;    // 64
    load(0, 0); cp_commit();
    for (int it = 0; it < NIT; it++) {
        if (it + 1 < NIT) { load((it + 1) & 1, it + 1); cp_commit(); cp_wait<1>(); }
        else              { cp_wait<0>(); }
        __syncthreads();
        const bf16* s = smem + (it & 1) * STAGE;
        const bf16* sB = s + 2 * APL;
        #pragma unroll
        for (int kh = 0; kh < 2; kh++) {
            const int g = lane >> 3, l8 = lane & 7;
            uint32_t ah[2][4], al[2][4], bh[4][2], bl[4][2];
            int kA = kh*16 + ((g >> 1) << 3) + l8, mA = (g & 1) << 3;
            #pragma unroll
            for (int mi = 0; mi < 2; mi++) {
                int mrow = warpM*32 + mi*16 + mA;
                ldsm4t(ah[mi], sptr(s + kA*LDTA + mrow));
                ldsm4t(al[mi], sptr(s + APL + kA*LDTA + mrow));
            }
            int kB = kh*16 + ((g & 1) << 3) + l8, nB0 = (g >> 1) << 3;
            #pragma unroll
            for (int p = 0; p < 2; p++) {
                int ncol = warpN*32 + p*16 + nB0;
                uint32_t t[4];
                ldsm4t(t, sptr(sB + kB*LDTB + ncol));
                bh[2*p][0]=t[0]; bh[2*p][1]=t[1]; bh[2*p+1][0]=t[2]; bh[2*p+1][1]=t[3];
                ldsm4t(t, sptr(sB + BPL + kB*LDTB + ncol));
                bl[2*p][0]=t[0]; bl[2*p][1]=t[1]; bl[2*p+1][0]=t[2]; bl[2*p+1][1]=t[3];
            }
            if (doSN) {
                #pragma unroll
                for (int mi = 0; mi < 2; mi++) {
                    mma16816(accS[mi], ah[mi], bones);
                    mma16816(accS[mi], al[mi], bones);
                }
            }
            #pragma unroll
            for (int mi = 0; mi < 2; mi++)
                #pragma unroll
                for (int ni = 0; ni < 4; ni++) {
                    mma16816(acc[mi][ni], ah[mi], bh[ni]);
                    mma16816(acc[mi][ni], ah[mi], bl[ni]);
                    mma16816(acc[mi][ni], al[mi], bh[ni]);
                }
        }
        __syncthreads();
    }

    float* P = g_Ppart + (long)z * INNER_ * DIM_;
    #pragma unroll
    for (int mi = 0; mi < 2; mi++)
        #pragma unroll
        for (int ni = 0; ni < 4; ni++) {
            int col = nBase + warpN*32 + ni*8 + (lane & 3)*2;
            #pragma unroll
            for (int rh = 0; rh < 2; rh++) {
                int row = mBase + warpM*32 + mi*16 + rh*8 + (lane >> 2);
                *reinterpret_cast<float2*>(P + (long)row * DIM_ + col) =
                    make_float2(acc[mi][ni][rh*2], acc[mi][ni][rh*2+1]);
            }
        }
    if (doSN && (lane & 3) == 0) {
        #pragma unroll
        for (int mi = 0; mi < 2; mi++) {
            int r0 = mBase + warpM*32 + mi*16 + (lane >> 2);
            g_psn[(long)z * INNER_ + r0]     = accS[mi][0];
            g_psn[(long)z * INNER_ + r0 + 8] = accS[mi][2];
        }
    }
}

__global__ __launch_bounds__(256) void st_k(
    const float* __restrict__ Wfx, const float* __restrict__ bfx)
{
    extern __shared__ float Ps[];
    __shared__ float inv_sn[64], sn_s[64];
    const int bh = blockIdx.x, b = bh >> 3, h = bh & 7;
    const int tid = threadIdx.x;
    for (int e = tid; e < 64 * 256; e += 256) {
        int g = e >> 8, c = e & 255;
        float s = 0.f;
        #pragma unroll
        for (int sp = 0; sp < PSPLITS; sp++)
            s += g_Ppart[((long)(b*PSPLITS + sp) * INNER_ + h*64 + g) * DIM_ + c];
        Ps[g*257 + c] = s;
    }
    if (tid < 64) {
        float s = 0.f;
        #pragma unroll
        for (int sp = 0; sp < PSPLITS; sp++)
            s += g_psn[(long)(b*PSPLITS + sp) * INNER_ + h*64 + tid];
        sn_s[tid] = s;
        inv_sn[tid] = 1.0f / (s + 1e-5f);
    }
    __syncthreads();
    const int d = tid & 63, q = tid >> 6;
    const float bfxd = bfx[h*64 + d];
    const float* wrow = Wfx + (long)(h*64 + d) * DIM_;
    float acc[16] = {};
    for (int c = 0; c < 256; c++) {
        float w = wrow[c];
        #pragma unroll
        for (int i = 0; i < 16; i++) acc[i] += Ps[(q*16 + i)*257 + c] * w;
    }
    #pragma unroll
    for (int i = 0; i < 16; i++) {
        int g = q*16 + i;
        g_st[(long)bh * 4096 + g*64 + d] = (acc[i] + sn_s[g] * bfxd) * inv_sn[g];
    }
}

__global__ __launch_bounds__(256) void kv_k(
    const float* __restrict__ Wk, const float* __restrict__ Wv)
{
    __shared__ float kv[4096], kb[4096], rn[64];
    const int b = blockIdx.x, tid = threadIdx.x;
    for (int e = tid; e < 4096; e += 256) {
        float s = 0.f;
        #pragma unroll
        for (int h = 0; h < 8; h++) s += g_st[(long)(b*8 + h) * 4096 + e];
        kv[e] = s * 0.125f;
    }
    __syncthreads();
    {
        const int d = tid & 63;
        const float4* wkp = reinterpret_cast<const float4*>(Wk + d*64);
        const float4* wvp = reinterpret_cast<const float4*>(Wv + d*64);
        #pragma unroll
        for (int k = 0; k < 16; k++) {
            int g = (tid >> 6) + k*4;
            const float4* kvp = reinterpret_cast<const float4*>(kv + g*64);
            float sk = 0.f, sv = 0.f;
            #pragma unroll
            for (int e4 = 0; e4 < 16; e4++) {
                float4 x = kvp[e4], w1 = wkp[e4], w2 = wvp[e4];
                sk += x.x*w1.x + x.y*w1.y + x.z*w1.z + x.w*w1.w;
                sv += x.x*w2.x + x.y*w2.y + x.z*w2.z + x.w*w2.w;
            }
            kb[g*64 + d] = sk;
            g_v[(long)b * 4096 + g*64 + d] = sv;
        }
    }
    __syncthreads();
    if (tid < 64) {
        float s = 0.f;
        for (int d = 0; d < 64; d++) { float x = kb[tid*64 + d]; s += x*x; }
        rn[tid] = 1.0f / fmaxf(sqrtf(s), 1e-12f);
    }
    __syncthreads();
    for (int e = tid; e < 4096; e += 256)
        g_kn[(long)b * 4096 + e] = kb[e] * rn[e >> 6];
}

__global__ __launch_bounds__(256) void attn_k(
    const float* __restrict__ Wq, const float* __restrict__ Wout,
    const float* __restrict__ attn_scale, const float* __restrict__ res_scale)
{
    extern __shared__ float sm[];
    float* sst = sm;
    float* sq  = sm + 4096;
    float* sc  = sm + 8192;
    const int bh = blockIdx.x, b = bh >> 3, h = bh & 7;
    const int tid = threadIdx.x;

    for (int e = tid; e < 4096; e += 256) sst[e] = g_st[(long)bh * 4096 + e];
    __syncthreads();
    {
        const int d = tid & 63;
        const float4* wp = reinterpret_cast<const float4*>(Wq + d*64);
        #pragma unroll
        for (int k = 0; k < 16; k++) {
            int g = (tid >> 6) + k*4;
            const float4* sp = reinterpret_cast<const float4*>(sst + g*64);
            float s = 0.f;
            #pragma unroll
            for (int e4 = 0; e4 < 16; e4++) {
                float4 w = wp[e4], x = sp[e4];
                s += w.x*x.x + w.y*x.y + w.z*x.z + w.w*x.w;
            }
            sq[g*64 + d] = s;
        }
    }
    __syncthreads();
    if (tid < 64) {
        float s = 0.f;
        for (int d = 0; d < 64; d++) { float x = sq[tid*64 + d]; s += x*x; }
        float inv = 1.0f / fmaxf(sqrtf(s), 1e-12f);
        for (int d = 0; d < 64; d++) sq[tid*64 + d] *= inv;
    }
    __syncthreads();
    {
        const float asc = attn_scale[h];
        const int ss = tid & 63;
        const float4* kp = reinterpret_cast<const float4*>(g_kn + (long)b * 4096 + ss*64);
        #pragma unroll
        for (int k = 0; k < 16; k++) {
            int g = (tid >> 6) + k*4;
            const float4* qp = reinterpret_cast<const float4*>(sq + g*64);
            float s = 0.f;
            #pragma unroll
            for (int d4 = 0; d4 < 16; d4++) {
                float4 kk = kp[d4], qq = qp[d4];
                s += kk.x*qq.x + kk.y*qq.y + kk.z*qq.z + kk.w*qq.w;
            }
            sc[g*65 + ss] = s * asc;
        }
    }
    __syncthreads();
    if (tid < 64) {
        float m = -1e30f;
        for (int s = 0; s < 64; s++) m = fmaxf(m, sc[tid*65 + s]);
        float sum = 0.f;
        for (int s = 0; s < 64; s++) {
            float e = __expf(sc[tid*65 + s] - m);
            sc[tid*65 + s] = e; sum += e;
        }
        float inv = 1.0f / sum;
        for (int s = 0; s < 64; s++) sc[tid*65 + s] *= inv;
    }
    for (int e = tid; e < 4096; e += 256) sq[e] = g_v[(long)b * 4096 + e];
    __syncthreads();

    const float res = *res_scale;
    float outreg[16];
    {
        const int d = tid & 63;
        #pragma unroll
        for (int k = 0; k < 16; k++) {
            int g = (tid >> 6) + k*4;
            float s = 0.f;
            #pragma unroll 16
            for (int ss = 0; ss < 64; ss++) s += sc[g*65 + ss] * sq[ss*64 + d];
            outreg[k] = s + res * sst[g*64 + d];
        }
    }
    __syncthreads();
    {
        const int d = tid & 63;
        #pragma unroll
        for (int k = 0; k < 16; k++) sst[((tid >> 6) + k*4)*64 + d] = outreg[k];
    }
    __syncthreads();
    {
        const int c = tid;
        const float4* wp = reinterpret_cast<const float4*>(Wout + c*INNER_ + h*64);
        for (int g = 0; g < 64; g++) {
            const float4* op = reinterpret_cast<const float4*>(sst + g*64);
            float s = 0.f;
            #pragma unroll
            for (int d4 = 0; d4 < 16; d4++) {
                float4 w = wp[d4], o = op[d4];
                s += w.x*o.x + w.y*o.y + w.z*o.z + w.w*o.w;
            }
            g_M[((long)b * DIM_ + c) * INNER_ + h*64 + g] = s;
        }
    }
}

__global__ __launch_bounds__(256) void splitM_k() {
    int i = blockIdx.x * 256 + threadIdx.x;
    split1(g_M[i], g_MHi[i], g_MLo[i]);
}

extern "C" void kernel_launch(void* const* d_in, const int* in_sizes, int n_in,
                              void* d_out, int out_size)
{
    const float* x         = (const float*)d_in[0];
    const float* Wfx       = (const float*)d_in[1];
    const float* bfx       = (const float*)d_in[2];
    const float* Wx        = (const float*)d_in[3];
    const float* bx        = (const float*)d_in[4];
    const float* Wslice    = (const float*)d_in[5];
    const float* bslice    = (const float*)d_in[6];
    const float* temp      = (const float*)d_in[7];
    const float* Wq        = (const float*)d_in[8];
    const float* Wk        = (const float*)d_in[9];
    const float* Wv        = (const float*)d_in[10];
    const float* res_scale = (const float*)d_in[11];
    const float* attn_scl  = (const float*)d_in[12];
    const float* Wout      = (const float*)d_in[13];
    const float* bout      = (const float*)d_in[14];
    float* out = (float*)d_out;

    bf16 *p_xHi, *p_xLo, *p_swHi, *p_swLo, *p_WcHi, *p_WcLo, *p_MHi, *p_MLo;
    float *p_lbias;
    cudaGetSymbolAddress((void**)&p_xHi, g_xHi);
    cudaGetSymbolAddress((void**)&p_xLo, g_xLo);
    cudaGetSymbolAddress((void**)&p_swHi, g_swHi);
    cudaGetSymbolAddress((void**)&p_swLo, g_swLo);
    cudaGetSymbolAddress((void**)&p_WcHi, g_WcombHi);
    cudaGetSymbolAddress((void**)&p_WcLo, g_WcombLo);
    cudaGetSymbolAddress((void**)&p_MHi, g_MHi);
    cudaGetSymbolAddress((void**)&p_MLo, g_MLo);
    cudaGetSymbolAddress((void**)&p_lbias, g_lbias);

    const int GEMM_SMEM = 2 * 4 * 128 * LDA * (int)sizeof(bf16);            // 81920
    const int P_SMEM    = 2 * (2*32*LDTA + 2*32*LDTB) * (int)sizeof(bf16);  // 53248
    const int ST_SMEM   = 64 * 257 * (int)sizeof(float);
    cudaFuncSetAttribute(mma_gemm<true, true>,  cudaFuncAttributeMaxDynamicSharedMemorySize, GEMM_SMEM);
    cudaFuncSetAttribute(mma_gemm<false, false>, cudaFuncAttributeMaxDynamicSharedMemorySize, GEMM_SMEM);
    cudaFuncSetAttribute(pgemm_k, cudaFuncAttributeMaxDynamicSharedMemorySize, P_SMEM);
    cudaFuncSetAttribute(st_k, cudaFuncAttributeMaxDynamicSharedMemorySize, ST_SMEM);
    cudaFuncSetAttribute(attn_k, cudaFuncAttributeMaxDynamicSharedMemorySize, 49408);

    splitX_k<<<(B_ * NPTS * DIM_) / 4 / 256, 256>>>(x);
    prep_k<<<512, 256>>>(Wx, Wslice, bx, bslice);

    // sw = softmax_G((x @ Wcomb^T + lbias)/temp) -> bf16 hi/lo planes
    mma_gemm<true, true><<<dim3(1024, 4, 1), 256, GEMM_SMEM>>>(
        p_xHi, p_xLo, p_WcHi, p_WcLo, p_lbias, temp,
        nullptr, p_swHi, p_swLo, INNER_, DIM_, 0, 0, 0);

    // P[b] = sw[b]^T @ X[b] (split-K HMMA, snorm fused); tile 128x64, 2 blk/SM
    pgemm_k<<<dim3(4, 4, B_ * PSPLITS), 256, P_SMEM>>>();

    st_k<<<BH_, 256, ST_SMEM>>>(Wfx, bfx);
    kv_k<<<B_, 256>>>(Wk, Wv);
    attn_k<<<BH_, 256, 49408>>>(Wq, Wout, attn_scl, res_scale);
    splitM_k<<<2048, 256>>>();

    // out = sw @ M[b]^T + bout
    mma_gemm<false, false><<<dim3(256, 2, B_), 256, GEMM_SMEM>>>(
        p_swHi, p_swLo, p_MHi, p_MLo, bout, nullptr,
        out, nullptr, nullptr, DIM_, INNER_,
        (long)NPTS * INNER_, (long)DIM_ * INNER_, (long)NPTS * DIM_);
}